// round 7
// baseline (speedup 1.0000x reference)
#include <cuda_runtime.h>
#include <math.h>
#include <stdint.h>

// ---------------- problem constants ----------------
#define B_    8
#define T_    4096
#define DIM_  1024
#define DIN_  512
#define DBR_  256
#define HBR_  8
#define TP_   4100      // padded length (-4096 % 10 == -4096 % 20 == 4)
#define NW1_  410
#define NW2_  205

// ---------------- device scratch (static) ----------------
__device__ float g_xi  [B_*T_*DIN_];
__device__ float g_x1p [B_*TP_*DBR_];
__device__ float g_x2p [B_*TP_*DBR_];
__device__ float g_qkv1[B_*TP_*3*DBR_];
__device__ float g_qkv2[B_*TP_*3*DBR_];
__device__ float g_ao1 [B_*TP_*DBR_];
__device__ float g_ao2 [B_*TP_*DBR_];
__device__ float g_po1 [B_*TP_*DBR_];
__device__ float g_po2 [B_*TP_*DBR_];
__device__ float g_xcat[B_*T_*DIN_];
__device__ float g_xmid[B_*T_*DIM_];
__device__ float g_h   [B_*T_*DIM_];
__device__ float g_ffn [B_*T_*2*DIM_];
__device__ float g_wt  [5767168];   // transposed (K-major) weights

// offsets (floats) into g_wt
#define O_DOWN  0u          // [512,1024]
#define O_UP    524288u     // [1024,512]
#define O_QKV1  1048576u    // [768,256]
#define O_QKV2  1245184u
#define O_PROJ1 1441792u    // [256,256]
#define O_PROJ2 1507328u
#define O_FFN1  1572864u    // [2048,1024]
#define O_FFN2  3670016u    // [1024,2048]

// ---------------- small PTX helpers (base ISA only) ----------
__device__ __forceinline__ uint32_t smem_u32(const void* p) {
    uint32_t a;
    asm("{ .reg .u64 t; cvta.to.shared.u64 t, %1; cvt.u32.u64 %0, t; }" : "=r"(a) : "l"(p));
    return a;
}
__device__ __forceinline__ uint32_t f2tf32(float f) {
    uint32_t r; asm("cvt.rna.tf32.f32 %0, %1;" : "=r"(r) : "f"(f)); return r;
}
__device__ __forceinline__ void mma_tf32(float* d, const uint32_t* a, const uint32_t* b) {
    asm volatile(
        "mma.sync.aligned.m16n8k8.row.col.f32.tf32.tf32.f32 "
        "{%0,%1,%2,%3}, {%4,%5,%6,%7}, {%8,%9}, {%0,%1,%2,%3};"
        : "+f"(d[0]), "+f"(d[1]), "+f"(d[2]), "+f"(d[3])
        : "r"(a[0]), "r"(a[1]), "r"(a[2]), "r"(a[3]), "r"(b[0]), "r"(b[1]));
}
__device__ __forceinline__ void cp_async16(uint32_t dst, const void* src, int szBytes) {
    asm volatile("cp.async.cg.shared.global [%0], [%1], 16, %2;"
                 :: "r"(dst), "l"(src), "r"(szBytes));
}
__device__ __forceinline__ void cp_async16f(uint32_t dst, const void* src) {
    asm volatile("cp.async.cg.shared.global [%0], [%1], 16;"
                 :: "r"(dst), "l"(src));
}
__device__ __forceinline__ void cp_commit() { asm volatile("cp.async.commit_group;" ::: "memory"); }
__device__ __forceinline__ void cp_wait2()  { asm volatile("cp.async.wait_group 2;" ::: "memory"); }
__device__ __forceinline__ void cp_wait1()  { asm volatile("cp.async.wait_group 1;" ::: "memory"); }
__device__ __forceinline__ void cp_wait0()  { asm volatile("cp.async.wait_group 0;" ::: "memory"); }

// ---------------- warp-mma tf32 GEMM ----------------
// C[M,N] = A[M,K] @ Wt[N,K]^T + bias    (Wt K-major, pre-rounded to tf32)
// mode 0: plain   mode 1: exact GELU    mode 2: += res[M,N]
// CTA tile 128x256, 8 warps (2x4), warp tile 64x64, K-chunk 32, 3-stage cp.async.
// Requires N % 256 == 0, K % 32 == 0. M guarded.
#define GBM 128
#define GBN 256
#define GBK 32
#define AST 36                                  // 32 + 4 pad (floats)
#define STAGE_F ((GBM + GBN) * AST)             // 13824 floats per stage
#define GEMM_SMEM (3 * STAGE_F * 4)             // 165888 bytes

__device__ __forceinline__ void stage_loads(
    const float* __restrict__ A, const float* __restrict__ Wt,
    int M, int K, int rowBase, int colBase, int k0,
    uint32_t asBase, uint32_t bsBase, int tid)
{
    // A: 128 rows x 8 chunks(16B) = 1024 slots
    #pragma unroll
    for (int i = 0; i < 4; i++) {
        int idx = tid + i * 256;
        int r = idx >> 3, c = (idx & 7) << 2;
        int gr = rowBase + r;
        int sz = (gr < M) ? 16 : 0;
        if (gr >= M) gr = M - 1;                // keep address valid (zero-filled)
        cp_async16(asBase + (uint32_t)(r * AST + c) * 4u,
                   A + (size_t)gr * K + k0 + c, sz);
    }
    // B: 256 rows x 8 chunks = 2048 slots
    #pragma unroll
    for (int i = 0; i < 8; i++) {
        int idx = tid + i * 256;
        int r = idx >> 3, c = (idx & 7) << 2;
        cp_async16f(bsBase + (uint32_t)(r * AST + c) * 4u,
                    Wt + (size_t)(colBase + r) * K + k0 + c);
    }
    cp_commit();
}

__global__ __launch_bounds__(256, 1)
void mma_gemm(const float* __restrict__ A, const float* __restrict__ Wt,
              const float* __restrict__ bias, const float* __restrict__ res,
              float* __restrict__ C, int M, int N, int K, int mode)
{
    extern __shared__ float sm[];
    const uint32_t smBase = smem_u32(sm);

    const int tid  = threadIdx.x;
    const int wid  = tid >> 5;
    const int lane = tid & 31;
    const int g    = lane >> 2;       // 0..7
    const int tg   = lane & 3;        // 0..3
    const int warpRow = wid >> 2;     // 0..1 -> 64-row band
    const int warpCol = wid & 3;      // 0..3 -> 64-col band
    const int rowBase = blockIdx.y * GBM;
    const int colBase = blockIdx.x * GBN;

    float acc[4][8][4];
    #pragma unroll
    for (int mt = 0; mt < 4; mt++)
        #pragma unroll
        for (int nt = 0; nt < 8; nt++)
            #pragma unroll
            for (int i = 0; i < 4; i++) acc[mt][nt][i] = 0.f;

    const int nk = K >> 5;
    // prologue: stages 0, 1
    stage_loads(A, Wt, M, K, rowBase, colBase, 0,
                smBase, smBase + GBM * AST * 4u, tid);
    if (nk > 1) {
        const uint32_t b1 = smBase + (uint32_t)STAGE_F * 4u;
        stage_loads(A, Wt, M, K, rowBase, colBase, 32,
                    b1, b1 + GBM * AST * 4u, tid);
    }

    for (int kc = 0; kc < nk; kc++) {
        const int s = kc % 3;
        if (kc + 2 < nk) {
            const uint32_t nb = smBase + (uint32_t)(((kc + 2) % 3) * STAGE_F) * 4u;
            stage_loads(A, Wt, M, K, rowBase, colBase, (kc + 2) << 5,
                        nb, nb + GBM * AST * 4u, tid);
            cp_wait2();
        } else if (kc + 1 < nk) {
            cp_wait1();
        } else {
            cp_wait0();
        }
        __syncthreads();

        const float* as = sm + s * STAGE_F;
        const float* bs = as + GBM * AST;
        const float* aw = as + (warpRow * 64 + g) * AST + tg;
        const float* bw = bs + (warpCol * 64 + g) * AST + tg;

        #pragma unroll
        for (int ks = 0; ks < 4; ks++) {
            const int k = ks * 8;
            uint32_t afr[4][4], bfr[8][2];
            #pragma unroll
            for (int mt = 0; mt < 4; mt++) {
                const float* ap = aw + mt * 16 * AST + k;
                afr[mt][0] = f2tf32(ap[0]);
                afr[mt][1] = f2tf32(ap[8 * AST]);
                afr[mt][2] = f2tf32(ap[4]);
                afr[mt][3] = f2tf32(ap[8 * AST + 4]);
            }
            #pragma unroll
            for (int nt = 0; nt < 8; nt++) {
                const float* bp = bw + nt * 8 * AST + k;
                bfr[nt][0] = __float_as_uint(bp[0]);   // pre-rounded tf32
                bfr[nt][1] = __float_as_uint(bp[4]);
            }
            #pragma unroll
            for (int mt = 0; mt < 4; mt++)
                #pragma unroll
                for (int nt = 0; nt < 8; nt++)
                    mma_tf32(acc[mt][nt], afr[mt], bfr[nt]);
        }
        __syncthreads();
    }

    // ---------------- epilogue ----------------
    #pragma unroll
    for (int mt = 0; mt < 4; mt++) {
        #pragma unroll
        for (int nt = 0; nt < 8; nt++) {
            const int r0 = rowBase + warpRow * 64 + mt * 16 + g;
            const int cc = colBase + warpCol * 64 + nt * 8 + 2 * tg;
            const float bx = bias[cc], by = bias[cc + 1];
            #pragma unroll
            for (int h = 0; h < 2; h++) {
                const int row = r0 + h * 8;
                if (row >= M) continue;
                float v0 = acc[mt][nt][2 * h + 0] + bx;
                float v1 = acc[mt][nt][2 * h + 1] + by;
                if (mode == 1) {
                    v0 = 0.5f * v0 * (1.0f + erff(v0 * 0.70710678118654752f));
                    v1 = 0.5f * v1 * (1.0f + erff(v1 * 0.70710678118654752f));
                } else if (mode == 2) {
                    const float2 rv = *(const float2*)(res + (size_t)row * N + cc);
                    v0 += rv.x; v1 += rv.y;
                }
                *(float2*)(C + (size_t)row * N + cc) = make_float2(v0, v1);
            }
        }
    }
}

// ---------------- weight transpose: src[K,N] -> dst[N,K], rounded to tf32 ----
__global__ void transpose_kernel(const float* __restrict__ src, float* __restrict__ dst,
                                 int K, int N)
{
    __shared__ float t[32][33];
    const int kb = blockIdx.y * 32, nb = blockIdx.x * 32;
    const int x = threadIdx.x, y = threadIdx.y;
    #pragma unroll
    for (int i = 0; i < 32; i += 8)
        t[y + i][x] = src[(size_t)(kb + y + i) * N + nb + x];
    __syncthreads();
    #pragma unroll
    for (int i = 0; i < 32; i += 8)
        dst[(size_t)(nb + y + i) * K + kb + x] = __uint_as_float(f2tf32(t[x][y + i]));
}

// ---------------- RMSNorm ----------------
__global__ void rmsnorm_kernel(const float* __restrict__ in, const float* __restrict__ w,
                               float* __restrict__ out, int C)
{
    const int row = blockIdx.x;
    const float* p = in + (size_t)row * C;
    float s = 0.f;
    for (int c = threadIdx.x; c < C; c += blockDim.x) { float v = p[c]; s += v * v; }
    #pragma unroll
    for (int o = 16; o > 0; o >>= 1) s += __shfl_xor_sync(0xffffffffu, s, o);
    __shared__ float red[8];
    __shared__ float scale;
    int wid = threadIdx.x >> 5, lane = threadIdx.x & 31;
    if (lane == 0) red[wid] = s;
    __syncthreads();
    if (threadIdx.x == 0) {
        float t = 0.f;
        for (int i = 0; i < (int)(blockDim.x >> 5); i++) t += red[i];
        scale = rsqrtf(t / (float)C + 1e-6f);
    }
    __syncthreads();
    float sc = scale;
    for (int c = threadIdx.x; c < C; c += blockDim.x)
        out[(size_t)row * C + c] = p[c] * sc * w[c];
}

// ---------------- pad + roll(-shift) + split ----------------
__global__ void pack_kernel(const float* __restrict__ xi, float* __restrict__ xp,
                            int off, int shift)
{
    int idx = blockIdx.x * blockDim.x + threadIdx.x;
    const int total = B_ * TP_ * DBR_;
    if (idx >= total) return;
    int c = idx & (DBR_ - 1);
    int t = (idx / DBR_) % TP_;
    int b = idx / (DBR_ * TP_);
    int ts = t + shift; if (ts >= TP_) ts -= TP_;
    float v = 0.f;
    if (ts < T_) v = xi[((size_t)b * T_ + ts) * DIN_ + off + c];
    xp[idx] = v;
}

// ---------------- roll(+shift), truncate, concat ----------------
__global__ void unshift_kernel(const float* __restrict__ po, float* __restrict__ xcat,
                               int off, int shift)
{
    int idx = blockIdx.x * blockDim.x + threadIdx.x;
    const int total = B_ * TP_ * DBR_;
    if (idx >= total) return;
    int c = idx & (DBR_ - 1);
    int r = (idx / DBR_) % TP_;
    int b = idx / (DBR_ * TP_);
    int t = r + shift; if (t >= TP_) t -= TP_;
    if (t < T_) xcat[((size_t)b * T_ + t) * DIN_ + off + c] = po[idx];
}

// ---------------- windowed attention (warp per b,window,head) ----------------
#define ATT_SLICE 2336
__global__ __launch_bounds__(128)
void attn_kernel(const float* __restrict__ qkv, float* __restrict__ ao,
                 const float* __restrict__ rpb, int w, int nW, int shift)
{
    __shared__ float sm[4 * ATT_SLICE];
    const int warp = threadIdx.x >> 5, lane = threadIdx.x & 31;
    float* S = sm + warp * ATT_SLICE;
    const int gw = blockIdx.x * 4 + warp;
    const int h = gw & 7;
    const int n = (gw >> 3) % nW;
    const int b = gw / (8 * nW);

    float* q  = S;
    float* k  = S + w * 32;
    float* v  = S + 2 * w * 32;
    float* lg = S + 3 * w * 32;

    const size_t rbase = (size_t)b * TP_ + (size_t)n * w;
    for (int i = 0; i < w; i++) {
        size_t ro = (rbase + i) * 768 + h * 32 + lane;
        q[i * 32 + lane] = qkv[ro];
        k[i * 32 + lane] = qkv[ro + 256];
        v[i * 32 + lane] = qkv[ro + 512];
    }
    __syncwarp();

    const float scale = 0.17677669529663687f;
    const bool lastwin = (n == nW - 1);
    for (int p = lane; p < w * w; p += 32) {
        int i = p / w, j = p % w;
        float s = 0.f;
        #pragma unroll
        for (int d = 0; d < 32; d++) s = fmaf(q[i * 32 + d], k[j * 32 + d], s);
        s *= scale;
        s += rpb[(i - j + w - 1) * 8 + h];
        if (lastwin) {
            int mi = (i >= w - shift) ? 2 : 1;
            int mj = (j >= w - shift) ? 2 : 1;
            if (mi != mj) s -= 100.f;
        }
        lg[p] = s;
    }
    __syncwarp();

    if (lane < w) {
        float mx = -3.0e38f;
        for (int j = 0; j < w; j++) mx = fmaxf(mx, lg[lane * w + j]);
        float sum = 0.f;
        for (int j = 0; j < w; j++) { float e = expf(lg[lane * w + j] - mx); lg[lane * w + j] = e; sum += e; }
        float inv = 1.f / sum;
        for (int j = 0; j < w; j++) lg[lane * w + j] *= inv;
    }
    __syncwarp();

    for (int i = 0; i < w; i++) {
        float a = 0.f;
        for (int j = 0; j < w; j++) a = fmaf(lg[i * w + j], v[j * 32 + lane], a);
        ao[(rbase + i) * 256 + h * 32 + lane] = a;
    }
}

// ---------------- launch ----------------
extern "C" void kernel_launch(void* const* d_in, const int* in_sizes, int n_in,
                              void* d_out, int out_size)
{
    (void)in_sizes; (void)n_in; (void)out_size;
    const float* x       = (const float*)d_in[0];
    const float* down_w  = (const float*)d_in[1];
    const float* down_b  = (const float*)d_in[2];
    const float* up_w    = (const float*)d_in[3];
    const float* up_b    = (const float*)d_in[4];
    const float* n1w     = (const float*)d_in[5];
    const float* n2w     = (const float*)d_in[6];
    const float* qkv1_w  = (const float*)d_in[7];
    const float* qkv1_b  = (const float*)d_in[8];
    const float* proj1_w = (const float*)d_in[9];
    const float* proj1_b = (const float*)d_in[10];
    const float* rpb1    = (const float*)d_in[11];
    const float* qkv2_w  = (const float*)d_in[12];
    const float* qkv2_b  = (const float*)d_in[13];
    const float* proj2_w = (const float*)d_in[14];
    const float* proj2_b = (const float*)d_in[15];
    const float* rpb2    = (const float*)d_in[16];
    const float* ffn_w1  = (const float*)d_in[17];
    const float* ffn_b1  = (const float*)d_in[18];
    const float* ffn_w2  = (const float*)d_in[19];
    const float* ffn_b2  = (const float*)d_in[20];
    float* out = (float*)d_out;

    float *xi, *x1p, *x2p, *qk1, *qk2, *ao1, *ao2, *po1, *po2, *xcat, *xmid, *hbuf, *ffn, *wt;
    cudaGetSymbolAddress((void**)&xi,   g_xi);
    cudaGetSymbolAddress((void**)&x1p,  g_x1p);
    cudaGetSymbolAddress((void**)&x2p,  g_x2p);
    cudaGetSymbolAddress((void**)&qk1,  g_qkv1);
    cudaGetSymbolAddress((void**)&qk2,  g_qkv2);
    cudaGetSymbolAddress((void**)&ao1,  g_ao1);
    cudaGetSymbolAddress((void**)&ao2,  g_ao2);
    cudaGetSymbolAddress((void**)&po1,  g_po1);
    cudaGetSymbolAddress((void**)&po2,  g_po2);
    cudaGetSymbolAddress((void**)&xcat, g_xcat);
    cudaGetSymbolAddress((void**)&xmid, g_xmid);
    cudaGetSymbolAddress((void**)&hbuf, g_h);
    cudaGetSymbolAddress((void**)&ffn,  g_ffn);
    cudaGetSymbolAddress((void**)&wt,   g_wt);

    cudaFuncSetAttribute(mma_gemm, cudaFuncAttributeMaxDynamicSharedMemorySize, GEMM_SMEM);

    const int MT = B_ * T_;    // 32768
    const int MP = B_ * TP_;   // 32800
    const int PACK_TOT = B_ * TP_ * DBR_;
    const int MT_TILES = MT / GBM;              // 256
    const int MP_TILES = (MP + GBM - 1) / GBM;  // 257

    // 0. transpose all weights to K-major (tf32-rounded)
    transpose_kernel<<<dim3(DIN_/32,  DIM_/32),   dim3(32,8)>>>(down_w,  wt + O_DOWN,  DIM_,  DIN_);
    transpose_kernel<<<dim3(DIM_/32,  DIN_/32),   dim3(32,8)>>>(up_w,    wt + O_UP,    DIN_,  DIM_);
    transpose_kernel<<<dim3(768/32,   DBR_/32),   dim3(32,8)>>>(qkv1_w,  wt + O_QKV1,  DBR_,  768);
    transpose_kernel<<<dim3(768/32,   DBR_/32),   dim3(32,8)>>>(qkv2_w,  wt + O_QKV2,  DBR_,  768);
    transpose_kernel<<<dim3(DBR_/32,  DBR_/32),   dim3(32,8)>>>(proj1_w, wt + O_PROJ1, DBR_,  DBR_);
    transpose_kernel<<<dim3(DBR_/32,  DBR_/32),   dim3(32,8)>>>(proj2_w, wt + O_PROJ2, DBR_,  DBR_);
    transpose_kernel<<<dim3(2*DIM_/32, DIM_/32),  dim3(32,8)>>>(ffn_w1,  wt + O_FFN1,  DIM_,  2*DIM_);
    transpose_kernel<<<dim3(DIM_/32,  2*DIM_/32), dim3(32,8)>>>(ffn_w2,  wt + O_FFN2,  2*DIM_, DIM_);

    // 1. down + rmsnorm1
    mma_gemm<<<dim3(DIN_/GBN, MT_TILES), 256, GEMM_SMEM>>>(
        x, wt + O_DOWN, down_b, nullptr, xi, MT, DIN_, DIM_, 0);
    rmsnorm_kernel<<<MT, 256>>>(xi, n1w, xi, DIN_);

    // 2. pack
    pack_kernel<<<(PACK_TOT + 255) / 256, 256>>>(xi, x1p, 0,    5);
    pack_kernel<<<(PACK_TOT + 255) / 256, 256>>>(xi, x2p, DBR_, 10);

    // 3. QKV
    mma_gemm<<<dim3(768/GBN, MP_TILES), 256, GEMM_SMEM>>>(
        x1p, wt + O_QKV1, qkv1_b, nullptr, qk1, MP, 768, DBR_, 0);
    mma_gemm<<<dim3(768/GBN, MP_TILES), 256, GEMM_SMEM>>>(
        x2p, wt + O_QKV2, qkv2_b, nullptr, qk2, MP, 768, DBR_, 0);

    // 4. attention
    attn_kernel<<<B_ * NW1_ * HBR_ / 4, 128>>>(qk1, ao1, rpb1, 10, NW1_, 5);
    attn_kernel<<<B_ * NW2_ * HBR_ / 4, 128>>>(qk2, ao2, rpb2, 20, NW2_, 10);

    // 5. proj
    mma_gemm<<<dim3(DBR_/GBN, MP_TILES), 256, GEMM_SMEM>>>(
        ao1, wt + O_PROJ1, proj1_b, nullptr, po1, MP, DBR_, DBR_, 0);
    mma_gemm<<<dim3(DBR_/GBN, MP_TILES), 256, GEMM_SMEM>>>(
        ao2, wt + O_PROJ2, proj2_b, nullptr, po2, MP, DBR_, DBR_, 0);

    // 6. unshift + concat
    unshift_kernel<<<(PACK_TOT + 255) / 256, 256>>>(po1, xcat, 0,    5);
    unshift_kernel<<<(PACK_TOT + 255) / 256, 256>>>(po2, xcat, DBR_, 10);

    // 7. up + residual
    mma_gemm<<<dim3(DIM_/GBN, MT_TILES), 256, GEMM_SMEM>>>(
        xcat, wt + O_UP, up_b, x, xmid, MT, DIM_, DIN_, 2);

    // 8. rmsnorm2
    rmsnorm_kernel<<<MT, 256>>>(xmid, n2w, hbuf, DIM_);

    // 9. FFN1 + GELU
    mma_gemm<<<dim3(2*DIM_/GBN, MT_TILES), 256, GEMM_SMEM>>>(
        hbuf, wt + O_FFN1, ffn_b1, nullptr, ffn, MT, 2*DIM_, DIM_, 1);

    // 10. FFN2 + residual -> out
    mma_gemm<<<dim3(DIM_/GBN, MT_TILES), 256, GEMM_SMEM>>>(
        ffn, wt + O_FFN2, ffn_b2, xmid, out, MT, DIM_, 2*DIM_, 2);
}

// round 8
// speedup vs baseline: 1.3980x; 1.3980x over previous
#include <cuda_runtime.h>
#include <cuda_fp16.h>
#include <math.h>
#include <stdint.h>

// ---------------- problem constants ----------------
#define B_    8
#define T_    4096
#define DIM_  1024
#define DIN_  512
#define DBR_  256
#define HBR_  8
#define TP_   4100      // padded length (-4096 % 10 == -4096 % 20 == 4)
#define NW1_  410
#define NW2_  205

// ---------------- device scratch (static) ----------------
__device__ float g_xi  [B_*T_*DIN_];
__device__ float g_x1p [B_*TP_*DBR_];
__device__ float g_x2p [B_*TP_*DBR_];
__device__ float g_qkv1[B_*TP_*3*DBR_];
__device__ float g_qkv2[B_*TP_*3*DBR_];
__device__ float g_ao1 [B_*TP_*DBR_];
__device__ float g_ao2 [B_*TP_*DBR_];
__device__ float g_po1 [B_*TP_*DBR_];
__device__ float g_po2 [B_*TP_*DBR_];
__device__ float g_xcat[B_*T_*DIN_];
__device__ float g_xmid[B_*T_*DIM_];
__device__ float g_h   [B_*T_*DIM_];
__device__ float g_ffn [B_*T_*2*DIM_];
__device__ float g_wt  [5767168];   // transposed (K-major) weights

// offsets (floats) into g_wt
#define O_DOWN  0u          // [512,1024]
#define O_UP    524288u     // [1024,512]
#define O_QKV1  1048576u    // [768,256]
#define O_QKV2  1245184u
#define O_PROJ1 1441792u    // [256,256]
#define O_PROJ2 1507328u
#define O_FFN1  1572864u    // [2048,1024]
#define O_FFN2  3670016u    // [1024,2048]

// ---------------- small PTX helpers (base ISA only) ----------
__device__ __forceinline__ uint32_t smem_u32(const void* p) {
    uint32_t a;
    asm("{ .reg .u64 t; cvta.to.shared.u64 t, %1; cvt.u32.u64 %0, t; }" : "=r"(a) : "l"(p));
    return a;
}
__device__ __forceinline__ uint32_t h2pack(float lo, float hi) {
    __half2 h = __floats2half2_rn(lo, hi);      // .x = lo (low 16 bits)
    return *reinterpret_cast<uint32_t*>(&h);
}
__device__ __forceinline__ void mma_f16(float* d, const uint32_t* a, const uint32_t* b) {
    asm volatile(
        "mma.sync.aligned.m16n8k16.row.col.f32.f16.f16.f32 "
        "{%0,%1,%2,%3}, {%4,%5,%6,%7}, {%8,%9}, {%0,%1,%2,%3};"
        : "+f"(d[0]), "+f"(d[1]), "+f"(d[2]), "+f"(d[3])
        : "r"(a[0]), "r"(a[1]), "r"(a[2]), "r"(a[3]), "r"(b[0]), "r"(b[1]));
}
__device__ __forceinline__ void cp_async16(uint32_t dst, const void* src, int szBytes) {
    asm volatile("cp.async.cg.shared.global [%0], [%1], 16, %2;"
                 :: "r"(dst), "l"(src), "r"(szBytes));
}
__device__ __forceinline__ void cp_async16f(uint32_t dst, const void* src) {
    asm volatile("cp.async.cg.shared.global [%0], [%1], 16;"
                 :: "r"(dst), "l"(src));
}
__device__ __forceinline__ void cp_commit() { asm volatile("cp.async.commit_group;" ::: "memory"); }
__device__ __forceinline__ void cp_wait2()  { asm volatile("cp.async.wait_group 2;" ::: "memory"); }
__device__ __forceinline__ void cp_wait1()  { asm volatile("cp.async.wait_group 1;" ::: "memory"); }
__device__ __forceinline__ void cp_wait0()  { asm volatile("cp.async.wait_group 0;" ::: "memory"); }

// ---------------- warp-mma fp16 GEMM (fp32 accumulate) ----------------
// C[M,N] = A[M,K] @ Wt[N,K]^T + bias    (Wt K-major fp32; operands cvt to fp16 in regs)
// mode 0: plain   mode 1: exact GELU    mode 2: += res[M,N]
// CTA tile 128x256, 8 warps (2x4), warp tile 64x64, K-chunk 32, 3-stage cp.async.
// Requires N % 256 == 0, K % 32 == 0. M guarded.
#define GBM 128
#define GBN 256
#define GBK 32
#define AST 40                                  // 32 + 8 pad (row stride ≡ 8 banks mod 32)
#define STAGE_F ((GBM + GBN) * AST)             // 15360 floats per stage
#define GEMM_SMEM (3 * STAGE_F * 4)             // 184320 bytes

__device__ __forceinline__ void stage_loads(
    const float* __restrict__ A, const float* __restrict__ Wt,
    int M, int K, int rowBase, int colBase, int k0,
    uint32_t asBase, uint32_t bsBase, int tid)
{
    // A: 128 rows x 8 chunks(16B) = 1024 slots
    #pragma unroll
    for (int i = 0; i < 4; i++) {
        int idx = tid + i * 256;
        int r = idx >> 3, c = (idx & 7) << 2;
        int gr = rowBase + r;
        int sz = (gr < M) ? 16 : 0;
        if (gr >= M) gr = M - 1;                // keep address valid (zero-filled)
        cp_async16(asBase + (uint32_t)(r * AST + c) * 4u,
                   A + (size_t)gr * K + k0 + c, sz);
    }
    // B: 256 rows x 8 chunks = 2048 slots
    #pragma unroll
    for (int i = 0; i < 8; i++) {
        int idx = tid + i * 256;
        int r = idx >> 3, c = (idx & 7) << 2;
        cp_async16f(bsBase + (uint32_t)(r * AST + c) * 4u,
                    Wt + (size_t)(colBase + r) * K + k0 + c);
    }
    cp_commit();
}

__global__ __launch_bounds__(256, 1)
void mma_gemm(const float* __restrict__ A, const float* __restrict__ Wt,
              const float* __restrict__ bias, const float* __restrict__ res,
              float* __restrict__ C, int M, int N, int K, int mode)
{
    extern __shared__ float sm[];
    const uint32_t smBase = smem_u32(sm);

    const int tid  = threadIdx.x;
    const int wid  = tid >> 5;
    const int lane = tid & 31;
    const int g    = lane >> 2;       // 0..7
    const int tg   = lane & 3;        // 0..3
    const int warpRow = wid >> 2;     // 0..1 -> 64-row band
    const int warpCol = wid & 3;      // 0..3 -> 64-col band
    const int rowBase = blockIdx.y * GBM;
    const int colBase = blockIdx.x * GBN;

    float acc[4][8][4];
    #pragma unroll
    for (int mt = 0; mt < 4; mt++)
        #pragma unroll
        for (int nt = 0; nt < 8; nt++)
            #pragma unroll
            for (int i = 0; i < 4; i++) acc[mt][nt][i] = 0.f;

    const int nk = K >> 5;
    // prologue: stages 0, 1
    stage_loads(A, Wt, M, K, rowBase, colBase, 0,
                smBase, smBase + GBM * AST * 4u, tid);
    if (nk > 1) {
        const uint32_t b1 = smBase + (uint32_t)STAGE_F * 4u;
        stage_loads(A, Wt, M, K, rowBase, colBase, 32,
                    b1, b1 + GBM * AST * 4u, tid);
    }

    for (int kc = 0; kc < nk; kc++) {
        const int s = kc % 3;
        if (kc + 2 < nk) {
            const uint32_t nb = smBase + (uint32_t)(((kc + 2) % 3) * STAGE_F) * 4u;
            stage_loads(A, Wt, M, K, rowBase, colBase, (kc + 2) << 5,
                        nb, nb + GBM * AST * 4u, tid);
            cp_wait2();
        } else if (kc + 1 < nk) {
            cp_wait1();
        } else {
            cp_wait0();
        }
        __syncthreads();

        const float* as = sm + s * STAGE_F;
        const float* bs = as + GBM * AST;
        const float* aw = as + (warpRow * 64 + g) * AST + 2 * tg;
        const float* bw = bs + (warpCol * 64 + g) * AST + 2 * tg;

        #pragma unroll
        for (int ks = 0; ks < 2; ks++) {
            const int k = ks * 16;
            uint32_t afr[4][4], bfr[8][2];
            #pragma unroll
            for (int mt = 0; mt < 4; mt++) {
                const float* ap = aw + mt * 16 * AST + k;
                float2 p0 = *(const float2*)(ap);                 // (g,    k+2tg)
                float2 p1 = *(const float2*)(ap + 8 * AST);       // (g+8,  k+2tg)
                float2 p2 = *(const float2*)(ap + 8);             // (g,    k+8+2tg)
                float2 p3 = *(const float2*)(ap + 8 * AST + 8);   // (g+8,  k+8+2tg)
                afr[mt][0] = h2pack(p0.x, p0.y);
                afr[mt][1] = h2pack(p1.x, p1.y);
                afr[mt][2] = h2pack(p2.x, p2.y);
                afr[mt][3] = h2pack(p3.x, p3.y);
            }
            #pragma unroll
            for (int nt = 0; nt < 8; nt++) {
                const float* bp = bw + nt * 8 * AST + k;
                float2 q0 = *(const float2*)(bp);                 // (n=g, k+2tg)
                float2 q1 = *(const float2*)(bp + 8);             // (n=g, k+8+2tg)
                bfr[nt][0] = h2pack(q0.x, q0.y);
                bfr[nt][1] = h2pack(q1.x, q1.y);
            }
            #pragma unroll
            for (int mt = 0; mt < 4; mt++)
                #pragma unroll
                for (int nt = 0; nt < 8; nt++)
                    mma_f16(acc[mt][nt], afr[mt], bfr[nt]);
        }
        __syncthreads();
    }

    // ---------------- epilogue ----------------
    #pragma unroll
    for (int mt = 0; mt < 4; mt++) {
        #pragma unroll
        for (int nt = 0; nt < 8; nt++) {
            const int r0 = rowBase + warpRow * 64 + mt * 16 + g;
            const int cc = colBase + warpCol * 64 + nt * 8 + 2 * tg;
            const float bx = bias[cc], by = bias[cc + 1];
            #pragma unroll
            for (int h = 0; h < 2; h++) {
                const int row = r0 + h * 8;
                if (row >= M) continue;
                float v0 = acc[mt][nt][2 * h + 0] + bx;
                float v1 = acc[mt][nt][2 * h + 1] + by;
                if (mode == 1) {
                    v0 = 0.5f * v0 * (1.0f + erff(v0 * 0.70710678118654752f));
                    v1 = 0.5f * v1 * (1.0f + erff(v1 * 0.70710678118654752f));
                } else if (mode == 2) {
                    const float2 rv = *(const float2*)(res + (size_t)row * N + cc);
                    v0 += rv.x; v1 += rv.y;
                }
                *(float2*)(C + (size_t)row * N + cc) = make_float2(v0, v1);
            }
        }
    }
}

// ---------------- weight transpose: src[K,N] -> dst[N,K] ----------------
__global__ void transpose_kernel(const float* __restrict__ src, float* __restrict__ dst,
                                 int K, int N)
{
    __shared__ float t[32][33];
    const int kb = blockIdx.y * 32, nb = blockIdx.x * 32;
    const int x = threadIdx.x, y = threadIdx.y;
    #pragma unroll
    for (int i = 0; i < 32; i += 8)
        t[y + i][x] = src[(size_t)(kb + y + i) * N + nb + x];
    __syncthreads();
    #pragma unroll
    for (int i = 0; i < 32; i += 8)
        dst[(size_t)(nb + y + i) * K + kb + x] = t[x][y + i];
}

// ---------------- RMSNorm (float4) ----------------
__global__ void rmsnorm_kernel(const float* __restrict__ in, const float* __restrict__ w,
                               float* __restrict__ out, int C)
{
    const int row = blockIdx.x;
    const float4* p4 = (const float4*)(in + (size_t)row * C);
    const float4* w4 = (const float4*)w;
    float4* o4 = (float4*)(out + (size_t)row * C);
    const int C4 = C >> 2;
    float s = 0.f;
    for (int c = threadIdx.x; c < C4; c += blockDim.x) {
        float4 v = p4[c];
        s += v.x * v.x + v.y * v.y + v.z * v.z + v.w * v.w;
    }
    #pragma unroll
    for (int o = 16; o > 0; o >>= 1) s += __shfl_xor_sync(0xffffffffu, s, o);
    __shared__ float red[8];
    __shared__ float scale;
    int wid = threadIdx.x >> 5, lane = threadIdx.x & 31;
    if (lane == 0) red[wid] = s;
    __syncthreads();
    if (threadIdx.x == 0) {
        float t = 0.f;
        for (int i = 0; i < (int)(blockDim.x >> 5); i++) t += red[i];
        scale = rsqrtf(t / (float)C + 1e-6f);
    }
    __syncthreads();
    float sc = scale;
    for (int c = threadIdx.x; c < C4; c += blockDim.x) {
        float4 v = p4[c], ww = w4[c];
        o4[c] = make_float4(v.x * sc * ww.x, v.y * sc * ww.y,
                            v.z * sc * ww.z, v.w * sc * ww.w);
    }
}

// ---------------- pad + roll(-shift) + split (float4) ----------------
__global__ void pack_kernel(const float* __restrict__ xi, float* __restrict__ xp,
                            int off, int shift)
{
    int idx = blockIdx.x * blockDim.x + threadIdx.x;
    const int total = B_ * TP_ * (DBR_ / 4);
    if (idx >= total) return;
    int c = (idx & 63) << 2;
    int t = (idx >> 6) % TP_;
    int b = idx / (64 * TP_);
    int ts = t + shift; if (ts >= TP_) ts -= TP_;
    float4 v = make_float4(0.f, 0.f, 0.f, 0.f);
    if (ts < T_) v = *(const float4*)(xi + ((size_t)b * T_ + ts) * DIN_ + off + c);
    *(float4*)(xp + (size_t)idx * 4) = v;
}

// ---------------- roll(+shift), truncate, concat (float4) ----------------
__global__ void unshift_kernel(const float* __restrict__ po, float* __restrict__ xcat,
                               int off, int shift)
{
    int idx = blockIdx.x * blockDim.x + threadIdx.x;
    const int total = B_ * TP_ * (DBR_ / 4);
    if (idx >= total) return;
    int c = (idx & 63) << 2;
    int r = (idx >> 6) % TP_;
    int b = idx / (64 * TP_);
    int t = r + shift; if (t >= TP_) t -= TP_;
    if (t < T_) {
        float4 v = *(const float4*)(po + (size_t)idx * 4);
        *(float4*)(xcat + ((size_t)b * T_ + t) * DIN_ + off + c) = v;
    }
}

// ---------------- windowed attention (warp per b,window,head) ----------------
#define ATT_SLICE 2336
__global__ __launch_bounds__(128)
void attn_kernel(const float* __restrict__ qkv, float* __restrict__ ao,
                 const float* __restrict__ rpb, int w, int nW, int shift)
{
    __shared__ float sm[4 * ATT_SLICE];
    const int warp = threadIdx.x >> 5, lane = threadIdx.x & 31;
    float* S = sm + warp * ATT_SLICE;
    const int gw = blockIdx.x * 4 + warp;
    const int h = gw & 7;
    const int n = (gw >> 3) % nW;
    const int b = gw / (8 * nW);

    float* q  = S;
    float* k  = S + w * 32;
    float* v  = S + 2 * w * 32;
    float* lg = S + 3 * w * 32;

    const size_t rbase = (size_t)b * TP_ + (size_t)n * w;
    for (int i = 0; i < w; i++) {
        size_t ro = (rbase + i) * 768 + h * 32 + lane;
        q[i * 32 + lane] = qkv[ro];
        k[i * 32 + lane] = qkv[ro + 256];
        v[i * 32 + lane] = qkv[ro + 512];
    }
    __syncwarp();

    const float scale = 0.17677669529663687f;
    const bool lastwin = (n == nW - 1);
    for (int p = lane; p < w * w; p += 32) {
        int i = p / w, j = p % w;
        float s = 0.f;
        #pragma unroll
        for (int d = 0; d < 32; d++) s = fmaf(q[i * 32 + d], k[j * 32 + d], s);
        s *= scale;
        s += rpb[(i - j + w - 1) * 8 + h];
        if (lastwin) {
            int mi = (i >= w - shift) ? 2 : 1;
            int mj = (j >= w - shift) ? 2 : 1;
            if (mi != mj) s -= 100.f;
        }
        lg[p] = s;
    }
    __syncwarp();

    if (lane < w) {
        float mx = -3.0e38f;
        for (int j = 0; j < w; j++) mx = fmaxf(mx, lg[lane * w + j]);
        float sum = 0.f;
        for (int j = 0; j < w; j++) { float e = expf(lg[lane * w + j] - mx); lg[lane * w + j] = e; sum += e; }
        float inv = 1.f / sum;
        for (int j = 0; j < w; j++) lg[lane * w + j] *= inv;
    }
    __syncwarp();

    for (int i = 0; i < w; i++) {
        float a = 0.f;
        for (int j = 0; j < w; j++) a = fmaf(lg[i * w + j], v[j * 32 + lane], a);
        ao[(rbase + i) * 256 + h * 32 + lane] = a;
    }
}

// ---------------- launch ----------------
extern "C" void kernel_launch(void* const* d_in, const int* in_sizes, int n_in,
                              void* d_out, int out_size)
{
    (void)in_sizes; (void)n_in; (void)out_size;
    const float* x       = (const float*)d_in[0];
    const float* down_w  = (const float*)d_in[1];
    const float* down_b  = (const float*)d_in[2];
    const float* up_w    = (const float*)d_in[3];
    const float* up_b    = (const float*)d_in[4];
    const float* n1w     = (const float*)d_in[5];
    const float* n2w     = (const float*)d_in[6];
    const float* qkv1_w  = (const float*)d_in[7];
    const float* qkv1_b  = (const float*)d_in[8];
    const float* proj1_w = (const float*)d_in[9];
    const float* proj1_b = (const float*)d_in[10];
    const float* rpb1    = (const float*)d_in[11];
    const float* qkv2_w  = (const float*)d_in[12];
    const float* qkv2_b  = (const float*)d_in[13];
    const float* proj2_w = (const float*)d_in[14];
    const float* proj2_b = (const float*)d_in[15];
    const float* rpb2    = (const float*)d_in[16];
    const float* ffn_w1  = (const float*)d_in[17];
    const float* ffn_b1  = (const float*)d_in[18];
    const float* ffn_w2  = (const float*)d_in[19];
    const float* ffn_b2  = (const float*)d_in[20];
    float* out = (float*)d_out;

    float *xi, *x1p, *x2p, *qk1, *qk2, *ao1, *ao2, *po1, *po2, *xcat, *xmid, *hbuf, *ffn, *wt;
    cudaGetSymbolAddress((void**)&xi,   g_xi);
    cudaGetSymbolAddress((void**)&x1p,  g_x1p);
    cudaGetSymbolAddress((void**)&x2p,  g_x2p);
    cudaGetSymbolAddress((void**)&qk1,  g_qkv1);
    cudaGetSymbolAddress((void**)&qk2,  g_qkv2);
    cudaGetSymbolAddress((void**)&ao1,  g_ao1);
    cudaGetSymbolAddress((void**)&ao2,  g_ao2);
    cudaGetSymbolAddress((void**)&po1,  g_po1);
    cudaGetSymbolAddress((void**)&po2,  g_po2);
    cudaGetSymbolAddress((void**)&xcat, g_xcat);
    cudaGetSymbolAddress((void**)&xmid, g_xmid);
    cudaGetSymbolAddress((void**)&hbuf, g_h);
    cudaGetSymbolAddress((void**)&ffn,  g_ffn);
    cudaGetSymbolAddress((void**)&wt,   g_wt);

    cudaFuncSetAttribute(mma_gemm, cudaFuncAttributeMaxDynamicSharedMemorySize, GEMM_SMEM);

    const int MT = B_ * T_;    // 32768
    const int MP = B_ * TP_;   // 32800
    const int PACK4 = B_ * TP_ * (DBR_ / 4);
    const int MT_TILES = MT / GBM;              // 256
    const int MP_TILES = (MP + GBM - 1) / GBM;  // 257

    // 0. transpose all weights to K-major
    transpose_kernel<<<dim3(DIN_/32,  DIM_/32),   dim3(32,8)>>>(down_w,  wt + O_DOWN,  DIM_,  DIN_);
    transpose_kernel<<<dim3(DIM_/32,  DIN_/32),   dim3(32,8)>>>(up_w,    wt + O_UP,    DIN_,  DIM_);
    transpose_kernel<<<dim3(768/32,   DBR_/32),   dim3(32,8)>>>(qkv1_w,  wt + O_QKV1,  DBR_,  768);
    transpose_kernel<<<dim3(768/32,   DBR_/32),   dim3(32,8)>>>(qkv2_w,  wt + O_QKV2,  DBR_,  768);
    transpose_kernel<<<dim3(DBR_/32,  DBR_/32),   dim3(32,8)>>>(proj1_w, wt + O_PROJ1, DBR_,  DBR_);
    transpose_kernel<<<dim3(DBR_/32,  DBR_/32),   dim3(32,8)>>>(proj2_w, wt + O_PROJ2, DBR_,  DBR_);
    transpose_kernel<<<dim3(2*DIM_/32, DIM_/32),  dim3(32,8)>>>(ffn_w1,  wt + O_FFN1,  DIM_,  2*DIM_);
    transpose_kernel<<<dim3(DIM_/32,  2*DIM_/32), dim3(32,8)>>>(ffn_w2,  wt + O_FFN2,  2*DIM_, DIM_);

    // 1. down + rmsnorm1
    mma_gemm<<<dim3(DIN_/GBN, MT_TILES), 256, GEMM_SMEM>>>(
        x, wt + O_DOWN, down_b, nullptr, xi, MT, DIN_, DIM_, 0);
    rmsnorm_kernel<<<MT, 256>>>(xi, n1w, xi, DIN_);

    // 2. pack
    pack_kernel<<<(PACK4 + 255) / 256, 256>>>(xi, x1p, 0,    5);
    pack_kernel<<<(PACK4 + 255) / 256, 256>>>(xi, x2p, DBR_, 10);

    // 3. QKV
    mma_gemm<<<dim3(768/GBN, MP_TILES), 256, GEMM_SMEM>>>(
        x1p, wt + O_QKV1, qkv1_b, nullptr, qk1, MP, 768, DBR_, 0);
    mma_gemm<<<dim3(768/GBN, MP_TILES), 256, GEMM_SMEM>>>(
        x2p, wt + O_QKV2, qkv2_b, nullptr, qk2, MP, 768, DBR_, 0);

    // 4. attention
    attn_kernel<<<B_ * NW1_ * HBR_ / 4, 128>>>(qk1, ao1, rpb1, 10, NW1_, 5);
    attn_kernel<<<B_ * NW2_ * HBR_ / 4, 128>>>(qk2, ao2, rpb2, 20, NW2_, 10);

    // 5. proj
    mma_gemm<<<dim3(DBR_/GBN, MP_TILES), 256, GEMM_SMEM>>>(
        ao1, wt + O_PROJ1, proj1_b, nullptr, po1, MP, DBR_, DBR_, 0);
    mma_gemm<<<dim3(DBR_/GBN, MP_TILES), 256, GEMM_SMEM>>>(
        ao2, wt + O_PROJ2, proj2_b, nullptr, po2, MP, DBR_, DBR_, 0);

    // 6. unshift + concat
    unshift_kernel<<<(PACK4 + 255) / 256, 256>>>(po1, xcat, 0,    5);
    unshift_kernel<<<(PACK4 + 255) / 256, 256>>>(po2, xcat, DBR_, 10);

    // 7. up + residual
    mma_gemm<<<dim3(DIM_/GBN, MT_TILES), 256, GEMM_SMEM>>>(
        xcat, wt + O_UP, up_b, x, xmid, MT, DIM_, DIN_, 2);

    // 8. rmsnorm2
    rmsnorm_kernel<<<MT, 256>>>(xmid, n2w, hbuf, DIM_);

    // 9. FFN1 + GELU
    mma_gemm<<<dim3(2*DIM_/GBN, MT_TILES), 256, GEMM_SMEM>>>(
        hbuf, wt + O_FFN1, ffn_b1, nullptr, ffn, MT, 2*DIM_, DIM_, 1);

    // 10. FFN2 + residual -> out
    mma_gemm<<<dim3(DIM_/GBN, MT_TILES), 256, GEMM_SMEM>>>(
        ffn, wt + O_FFN2, ffn_b2, xmid, out, MT, DIM_, 2*DIM_, 2);
}

// round 9
// speedup vs baseline: 1.4873x; 1.0639x over previous
#include <cuda_runtime.h>
#include <cuda_fp16.h>
#include <math.h>
#include <stdint.h>

// ---------------- problem constants ----------------
#define B_    8
#define T_    4096
#define DIM_  1024
#define DIN_  512
#define DBR_  256
#define HBR_  8
#define TP_   4100      // padded length (-4096 % 10 == -4096 % 20 == 4)
#define NW1_  410
#define NW2_  205

// ---------------- device scratch (static) ----------------
__device__ __half g_xh  [B_*T_*DIM_];       // fp16 copy of input x
__device__ float  g_xi  [B_*T_*DIN_];       // down output (fp32)
__device__ __half g_xih [B_*T_*DIN_];       // rmsnorm1 out (fp16)
__device__ __half g_x1p [B_*TP_*DBR_];
__device__ __half g_x2p [B_*TP_*DBR_];
__device__ float  g_qkv1[B_*TP_*3*DBR_];
__device__ float  g_qkv2[B_*TP_*3*DBR_];
__device__ __half g_ao1 [B_*TP_*DBR_];
__device__ __half g_ao2 [B_*TP_*DBR_];
__device__ __half g_po1 [B_*TP_*DBR_];
__device__ __half g_po2 [B_*TP_*DBR_];
__device__ __half g_xcat[B_*T_*DIN_];
__device__ float  g_xmid[B_*T_*DIM_];
__device__ __half g_h   [B_*T_*DIM_];       // rmsnorm2 out (fp16)
__device__ __half g_ffn [B_*T_*2*DIM_];     // gelu(ffn1) (fp16)
__device__ __half g_wt  [5767168];          // transposed (K-major) fp16 weights

// offsets (elements) into g_wt
#define O_DOWN  0u
#define O_UP    524288u
#define O_QKV1  1048576u
#define O_QKV2  1245184u
#define O_PROJ1 1441792u
#define O_PROJ2 1507328u
#define O_FFN1  1572864u
#define O_FFN2  3670016u

// ---------------- PTX helpers (base ISA only) ----------
__device__ __forceinline__ uint32_t smem_u32(const void* p) {
    uint32_t a;
    asm("{ .reg .u64 t; cvta.to.shared.u64 t, %1; cvt.u32.u64 %0, t; }" : "=r"(a) : "l"(p));
    return a;
}
__device__ __forceinline__ uint32_t h2pack(float lo, float hi) {
    __half2 h = __floats2half2_rn(lo, hi);
    return *reinterpret_cast<uint32_t*>(&h);
}
__device__ __forceinline__ void mma_f16(float* d, const uint32_t* a, const uint32_t* b) {
    asm volatile(
        "mma.sync.aligned.m16n8k16.row.col.f32.f16.f16.f32 "
        "{%0,%1,%2,%3}, {%4,%5,%6,%7}, {%8,%9}, {%0,%1,%2,%3};"
        : "+f"(d[0]), "+f"(d[1]), "+f"(d[2]), "+f"(d[3])
        : "r"(a[0]), "r"(a[1]), "r"(a[2]), "r"(a[3]), "r"(b[0]), "r"(b[1]));
}
__device__ __forceinline__ void ldsm_x4(uint32_t* r, uint32_t addr) {
    asm volatile("ldmatrix.sync.aligned.m8n8.x4.shared.b16 {%0,%1,%2,%3}, [%4];"
                 : "=r"(r[0]), "=r"(r[1]), "=r"(r[2]), "=r"(r[3]) : "r"(addr));
}
__device__ __forceinline__ void cp_async16(uint32_t dst, const void* src, int szBytes) {
    asm volatile("cp.async.cg.shared.global [%0], [%1], 16, %2;"
                 :: "r"(dst), "l"(src), "r"(szBytes));
}
__device__ __forceinline__ void cp_async16f(uint32_t dst, const void* src) {
    asm volatile("cp.async.cg.shared.global [%0], [%1], 16;"
                 :: "r"(dst), "l"(src));
}
__device__ __forceinline__ void cp_commit() { asm volatile("cp.async.commit_group;" ::: "memory"); }
__device__ __forceinline__ void cp_wait2()  { asm volatile("cp.async.wait_group 2;" ::: "memory"); }
__device__ __forceinline__ void cp_wait1()  { asm volatile("cp.async.wait_group 1;" ::: "memory"); }
__device__ __forceinline__ void cp_wait0()  { asm volatile("cp.async.wait_group 0;" ::: "memory"); }

// ---------------- fp16-storage warp-mma GEMM (fp32 accumulate) ----------------
// C[M,N] = A[M,K] @ Wt[N,K]^T + bias    (A, Wt fp16 in gmem/smem; ldmatrix fragments)
// mode 0: bias, fp32 out   mode 1: bias+GELU, fp16 out
// mode 2: bias+res, fp32 out   mode 3: bias, fp16 out
// CTA tile 128x256, 8 warps (2x4), warp tile 64x64, K-chunk 32, 3-stage cp.async.
// Requires N % 256 == 0, K % 32 == 0. M guarded.
#define GBM 128
#define GBN 256
#define ASTH 40                                 // halves per row stride (80B, conflict-free)
#define STAGE_H ((GBM + GBN) * ASTH)            // 15360 halves = 30720 B
#define GEMM_SMEM (3 * STAGE_H * 2)             // 92160 bytes

__device__ __forceinline__ void stage_loads(
    const __half* __restrict__ A, const __half* __restrict__ Wt,
    int M, int K, int rowBase, int colBase, int k0,
    uint32_t asBase, uint32_t bsBase, int tid)
{
    // A: 128 rows x 4 chunks(16B = 8 halves) = 512 slots
    #pragma unroll
    for (int i = 0; i < 2; i++) {
        int idx = tid + i * 256;                // 0..511
        int r = idx >> 2, c = (idx & 3) << 3;   // c in halves
        int gr = rowBase + r;
        int sz = (gr < M) ? 16 : 0;
        if (gr >= M) gr = M - 1;
        cp_async16(asBase + (uint32_t)(r * ASTH + c) * 2u,
                   A + (size_t)gr * K + k0 + c, sz);
    }
    // B: 256 rows x 4 chunks = 1024 slots
    #pragma unroll
    for (int i = 0; i < 4; i++) {
        int idx = tid + i * 256;
        int r = idx >> 2, c = (idx & 3) << 3;
        cp_async16f(bsBase + (uint32_t)(r * ASTH + c) * 2u,
                    Wt + (size_t)(colBase + r) * K + k0 + c);
    }
    cp_commit();
}

__global__ __launch_bounds__(256, 1)
void mma_gemm(const __half* __restrict__ A, const __half* __restrict__ Wt,
              const float* __restrict__ bias, const float* __restrict__ res,
              void* __restrict__ Cv, int M, int N, int K, int mode)
{
    extern __shared__ __half smh[];
    const uint32_t smBase = smem_u32(smh);

    const int tid  = threadIdx.x;
    const int wid  = tid >> 5;
    const int lane = tid & 31;
    const int g    = lane >> 2;       // 0..7
    const int tg   = lane & 3;        // 0..3
    const int warpRow = wid >> 2;     // 0..1 -> 64-row band
    const int warpCol = wid & 3;      // 0..3 -> 64-col band
    const int rowBase = blockIdx.y * GBM;
    const int colBase = blockIdx.x * GBN;

    float acc[4][8][4];
    #pragma unroll
    for (int mt = 0; mt < 4; mt++)
        #pragma unroll
        for (int nt = 0; nt < 8; nt++)
            #pragma unroll
            for (int i = 0; i < 4; i++) acc[mt][nt][i] = 0.f;

    const int nk = K >> 5;
    stage_loads(A, Wt, M, K, rowBase, colBase, 0,
                smBase, smBase + GBM * ASTH * 2u, tid);
    if (nk > 1) {
        const uint32_t b1 = smBase + (uint32_t)STAGE_H * 2u;
        stage_loads(A, Wt, M, K, rowBase, colBase, 32,
                    b1, b1 + GBM * ASTH * 2u, tid);
    }

    // per-lane ldmatrix base offsets (halves)
    const uint32_t aLaneOff = (uint32_t)((warpRow * 64 + (lane & 15)) * ASTH + (lane >> 4) * 8) * 2u;
    const uint32_t bLaneOff = (uint32_t)((warpCol * 64 + (lane & 7) + ((lane >> 4) << 3)) * ASTH
                                         + ((lane >> 3) & 1) * 8) * 2u;

    for (int kc = 0; kc < nk; kc++) {
        const int s = kc % 3;
        if (kc + 2 < nk) {
            const uint32_t nb = smBase + (uint32_t)(((kc + 2) % 3) * STAGE_H) * 2u;
            stage_loads(A, Wt, M, K, rowBase, colBase, (kc + 2) << 5,
                        nb, nb + GBM * ASTH * 2u, tid);
            cp_wait2();
        } else if (kc + 1 < nk) {
            cp_wait1();
        } else {
            cp_wait0();
        }
        __syncthreads();

        const uint32_t aBase = smBase + (uint32_t)(s * STAGE_H) * 2u + aLaneOff;
        const uint32_t bBase = smBase + (uint32_t)(s * STAGE_H + GBM * ASTH) * 2u + bLaneOff;

        #pragma unroll
        for (int ks = 0; ks < 2; ks++) {
            const uint32_t ko = (uint32_t)ks * 32u;   // 16 halves = 32 bytes
            uint32_t afr[4][4], bfr[8][2];
            #pragma unroll
            for (int mt = 0; mt < 4; mt++)
                ldsm_x4(afr[mt], aBase + (uint32_t)(mt * 16 * ASTH) * 2u + ko);
            #pragma unroll
            for (int ntp = 0; ntp < 4; ntp++) {
                uint32_t q[4];
                ldsm_x4(q, bBase + (uint32_t)(ntp * 16 * ASTH) * 2u + ko);
                bfr[2 * ntp + 0][0] = q[0]; bfr[2 * ntp + 0][1] = q[1];
                bfr[2 * ntp + 1][0] = q[2]; bfr[2 * ntp + 1][1] = q[3];
            }
            #pragma unroll
            for (int mt = 0; mt < 4; mt++)
                #pragma unroll
                for (int nt = 0; nt < 8; nt++)
                    mma_f16(acc[mt][nt], afr[mt], bfr[nt]);
        }
        __syncthreads();
    }

    // ---------------- epilogue ----------------
    float* Cf = (float*)Cv;
    __half* Ch = (__half*)Cv;
    #pragma unroll
    for (int mt = 0; mt < 4; mt++) {
        #pragma unroll
        for (int nt = 0; nt < 8; nt++) {
            const int r0 = rowBase + warpRow * 64 + mt * 16 + g;
            const int cc = colBase + warpCol * 64 + nt * 8 + 2 * tg;
            const float bx = bias[cc], by = bias[cc + 1];
            #pragma unroll
            for (int h = 0; h < 2; h++) {
                const int row = r0 + h * 8;
                if (row >= M) continue;
                float v0 = acc[mt][nt][2 * h + 0] + bx;
                float v1 = acc[mt][nt][2 * h + 1] + by;
                if (mode == 1) {
                    v0 = 0.5f * v0 * (1.0f + erff(v0 * 0.70710678118654752f));
                    v1 = 0.5f * v1 * (1.0f + erff(v1 * 0.70710678118654752f));
                    *(__half2*)(Ch + (size_t)row * N + cc) = __floats2half2_rn(v0, v1);
                } else if (mode == 3) {
                    *(__half2*)(Ch + (size_t)row * N + cc) = __floats2half2_rn(v0, v1);
                } else {
                    if (mode == 2) {
                        const float2 rv = *(const float2*)(res + (size_t)row * N + cc);
                        v0 += rv.x; v1 += rv.y;
                    }
                    *(float2*)(Cf + (size_t)row * N + cc) = make_float2(v0, v1);
                }
            }
        }
    }
}

// ---------------- weight transpose: src[K,N] fp32 -> dst[N,K] fp16 ----------------
__global__ void transpose_kernel(const float* __restrict__ src, __half* __restrict__ dst,
                                 int K, int N)
{
    __shared__ float t[32][33];
    const int kb = blockIdx.y * 32, nb = blockIdx.x * 32;
    const int x = threadIdx.x, y = threadIdx.y;
    #pragma unroll
    for (int i = 0; i < 32; i += 8)
        t[y + i][x] = src[(size_t)(kb + y + i) * N + nb + x];
    __syncthreads();
    #pragma unroll
    for (int i = 0; i < 32; i += 8)
        dst[(size_t)(nb + y + i) * K + kb + x] = __float2half(t[x][y + i]);
}

// ---------------- fp32 -> fp16 convert (16B out per thread) ----------------
__global__ void f2h_kernel(const float* __restrict__ in, __half* __restrict__ out, int n8)
{
    int idx = blockIdx.x * blockDim.x + threadIdx.x;
    if (idx >= n8) return;
    const float4* p = (const float4*)(in + (size_t)idx * 8);
    float4 a = p[0], b = p[1];
    uint4 u;
    u.x = h2pack(a.x, a.y); u.y = h2pack(a.z, a.w);
    u.z = h2pack(b.x, b.y); u.w = h2pack(b.z, b.w);
    *(uint4*)(out + (size_t)idx * 8) = u;
}

// ---------------- RMSNorm: fp32 in, fp16 out ----------------
__global__ void rmsnorm_kernel(const float* __restrict__ in, const float* __restrict__ w,
                               __half* __restrict__ out, int C)
{
    const int row = blockIdx.x;
    const float4* p4 = (const float4*)(in + (size_t)row * C);
    const float4* w4 = (const float4*)w;
    const int C4 = C >> 2;
    float s = 0.f;
    for (int c = threadIdx.x; c < C4; c += blockDim.x) {
        float4 v = p4[c];
        s += v.x * v.x + v.y * v.y + v.z * v.z + v.w * v.w;
    }
    #pragma unroll
    for (int o = 16; o > 0; o >>= 1) s += __shfl_xor_sync(0xffffffffu, s, o);
    __shared__ float red[8];
    __shared__ float scale;
    int wid = threadIdx.x >> 5, lane = threadIdx.x & 31;
    if (lane == 0) red[wid] = s;
    __syncthreads();
    if (threadIdx.x == 0) {
        float t = 0.f;
        for (int i = 0; i < (int)(blockDim.x >> 5); i++) t += red[i];
        scale = rsqrtf(t / (float)C + 1e-6f);
    }
    __syncthreads();
    float sc = scale;
    for (int c = threadIdx.x; c < C4; c += blockDim.x) {
        float4 v = p4[c], ww = w4[c];
        uint2 u;
        u.x = h2pack(v.x * sc * ww.x, v.y * sc * ww.y);
        u.y = h2pack(v.z * sc * ww.z, v.w * sc * ww.w);
        *(uint2*)(out + (size_t)row * C + c * 4) = u;
    }
}

// ---------------- pad + roll(-shift) + split (fp16, 16B) ----------------
__global__ void pack_kernel(const __half* __restrict__ xi, __half* __restrict__ xp,
                            int off, int shift)
{
    int idx = blockIdx.x * blockDim.x + threadIdx.x;
    const int total = B_ * TP_ * (DBR_ / 8);
    if (idx >= total) return;
    int c = (idx & 31) << 3;
    int t = (idx >> 5) % TP_;
    int b = idx / (32 * TP_);
    int ts = t + shift; if (ts >= TP_) ts -= TP_;
    uint4 v = make_uint4(0u, 0u, 0u, 0u);
    if (ts < T_) v = *(const uint4*)(xi + ((size_t)b * T_ + ts) * DIN_ + off + c);
    *(uint4*)(xp + (size_t)idx * 8) = v;
}

// ---------------- roll(+shift), truncate, concat (fp16, 16B) ----------------
__global__ void unshift_kernel(const __half* __restrict__ po, __half* __restrict__ xcat,
                               int off, int shift)
{
    int idx = blockIdx.x * blockDim.x + threadIdx.x;
    const int total = B_ * TP_ * (DBR_ / 8);
    if (idx >= total) return;
    int c = (idx & 31) << 3;
    int r = (idx >> 5) % TP_;
    int b = idx / (32 * TP_);
    int t = r + shift; if (t >= TP_) t -= TP_;
    if (t < T_) {
        uint4 v = *(const uint4*)(po + (size_t)idx * 8);
        *(uint4*)(xcat + ((size_t)b * T_ + t) * DIN_ + off + c) = v;
    }
}

// ---------------- windowed attention (warp per b,window,head); fp16 out ----------
#define ATT_SLICE 2336
__global__ __launch_bounds__(128)
void attn_kernel(const float* __restrict__ qkv, __half* __restrict__ ao,
                 const float* __restrict__ rpb, int w, int nW, int shift)
{
    __shared__ float sm[4 * ATT_SLICE];
    const int warp = threadIdx.x >> 5, lane = threadIdx.x & 31;
    float* S = sm + warp * ATT_SLICE;
    const int gw = blockIdx.x * 4 + warp;
    const int h = gw & 7;
    const int n = (gw >> 3) % nW;
    const int b = gw / (8 * nW);

    float* q  = S;
    float* k  = S + w * 32;
    float* v  = S + 2 * w * 32;
    float* lg = S + 3 * w * 32;

    const size_t rbase = (size_t)b * TP_ + (size_t)n * w;
    for (int i = 0; i < w; i++) {
        size_t ro = (rbase + i) * 768 + h * 32 + lane;
        q[i * 32 + lane] = qkv[ro];
        k[i * 32 + lane] = qkv[ro + 256];
        v[i * 32 + lane] = qkv[ro + 512];
    }
    __syncwarp();

    const float scale = 0.17677669529663687f;
    const bool lastwin = (n == nW - 1);
    for (int p = lane; p < w * w; p += 32) {
        int i = p / w, j = p % w;
        float s = 0.f;
        #pragma unroll
        for (int d = 0; d < 32; d++) s = fmaf(q[i * 32 + d], k[j * 32 + d], s);
        s *= scale;
        s += rpb[(i - j + w - 1) * 8 + h];
        if (lastwin) {
            int mi = (i >= w - shift) ? 2 : 1;
            int mj = (j >= w - shift) ? 2 : 1;
            if (mi != mj) s -= 100.f;
        }
        lg[p] = s;
    }
    __syncwarp();

    if (lane < w) {
        float mx = -3.0e38f;
        for (int j = 0; j < w; j++) mx = fmaxf(mx, lg[lane * w + j]);
        float sum = 0.f;
        for (int j = 0; j < w; j++) { float e = expf(lg[lane * w + j] - mx); lg[lane * w + j] = e; sum += e; }
        float inv = 1.f / sum;
        for (int j = 0; j < w; j++) lg[lane * w + j] *= inv;
    }
    __syncwarp();

    for (int i = 0; i < w; i++) {
        float a = 0.f;
        for (int j = 0; j < w; j++) a = fmaf(lg[i * w + j], v[j * 32 + lane], a);
        ao[(rbase + i) * 256 + h * 32 + lane] = __float2half(a);
    }
}

// ---------------- launch ----------------
extern "C" void kernel_launch(void* const* d_in, const int* in_sizes, int n_in,
                              void* d_out, int out_size)
{
    (void)in_sizes; (void)n_in; (void)out_size;
    const float* x       = (const float*)d_in[0];
    const float* down_w  = (const float*)d_in[1];
    const float* down_b  = (const float*)d_in[2];
    const float* up_w    = (const float*)d_in[3];
    const float* up_b    = (const float*)d_in[4];
    const float* n1w     = (const float*)d_in[5];
    const float* n2w     = (const float*)d_in[6];
    const float* qkv1_w  = (const float*)d_in[7];
    const float* qkv1_b  = (const float*)d_in[8];
    const float* proj1_w = (const float*)d_in[9];
    const float* proj1_b = (const float*)d_in[10];
    const float* rpb1    = (const float*)d_in[11];
    const float* qkv2_w  = (const float*)d_in[12];
    const float* qkv2_b  = (const float*)d_in[13];
    const float* proj2_w = (const float*)d_in[14];
    const float* proj2_b = (const float*)d_in[15];
    const float* rpb2    = (const float*)d_in[16];
    const float* ffn_w1  = (const float*)d_in[17];
    const float* ffn_b1  = (const float*)d_in[18];
    const float* ffn_w2  = (const float*)d_in[19];
    const float* ffn_b2  = (const float*)d_in[20];
    float* out = (float*)d_out;

    __half *xh, *xih, *x1p, *x2p, *ao1, *ao2, *po1, *po2, *xcat, *hbuf, *ffn, *wt;
    float *xi, *qk1, *qk2, *xmid;
    cudaGetSymbolAddress((void**)&xh,   g_xh);
    cudaGetSymbolAddress((void**)&xi,   g_xi);
    cudaGetSymbolAddress((void**)&xih,  g_xih);
    cudaGetSymbolAddress((void**)&x1p,  g_x1p);
    cudaGetSymbolAddress((void**)&x2p,  g_x2p);
    cudaGetSymbolAddress((void**)&qk1,  g_qkv1);
    cudaGetSymbolAddress((void**)&qk2,  g_qkv2);
    cudaGetSymbolAddress((void**)&ao1,  g_ao1);
    cudaGetSymbolAddress((void**)&ao2,  g_ao2);
    cudaGetSymbolAddress((void**)&po1,  g_po1);
    cudaGetSymbolAddress((void**)&po2,  g_po2);
    cudaGetSymbolAddress((void**)&xcat, g_xcat);
    cudaGetSymbolAddress((void**)&xmid, g_xmid);
    cudaGetSymbolAddress((void**)&hbuf, g_h);
    cudaGetSymbolAddress((void**)&ffn,  g_ffn);
    cudaGetSymbolAddress((void**)&wt,   g_wt);

    cudaFuncSetAttribute(mma_gemm, cudaFuncAttributeMaxDynamicSharedMemorySize, GEMM_SMEM);

    const int MT = B_ * T_;    // 32768
    const int MP = B_ * TP_;   // 32800
    const int PACK8 = B_ * TP_ * (DBR_ / 8);
    const int MT_TILES = MT / GBM;              // 256
    const int MP_TILES = (MP + GBM - 1) / GBM;  // 257

    // 0. transpose weights to K-major fp16 + convert x to fp16
    transpose_kernel<<<dim3(DIN_/32,  DIM_/32),   dim3(32,8)>>>(down_w,  wt + O_DOWN,  DIM_,  DIN_);
    transpose_kernel<<<dim3(DIM_/32,  DIN_/32),   dim3(32,8)>>>(up_w,    wt + O_UP,    DIN_,  DIM_);
    transpose_kernel<<<dim3(768/32,   DBR_/32),   dim3(32,8)>>>(qkv1_w,  wt + O_QKV1,  DBR_,  768);
    transpose_kernel<<<dim3(768/32,   DBR_/32),   dim3(32,8)>>>(qkv2_w,  wt + O_QKV2,  DBR_,  768);
    transpose_kernel<<<dim3(DBR_/32,  DBR_/32),   dim3(32,8)>>>(proj1_w, wt + O_PROJ1, DBR_,  DBR_);
    transpose_kernel<<<dim3(DBR_/32,  DBR_/32),   dim3(32,8)>>>(proj2_w, wt + O_PROJ2, DBR_,  DBR_);
    transpose_kernel<<<dim3(2*DIM_/32, DIM_/32),  dim3(32,8)>>>(ffn_w1,  wt + O_FFN1,  DIM_,  2*DIM_);
    transpose_kernel<<<dim3(DIM_/32,  2*DIM_/32), dim3(32,8)>>>(ffn_w2,  wt + O_FFN2,  2*DIM_, DIM_);
    f2h_kernel<<<(MT * DIM_ / 8 + 255) / 256, 256>>>(x, xh, MT * DIM_ / 8);

    // 1. down + rmsnorm1 (fp16 out)
    mma_gemm<<<dim3(DIN_/GBN, MT_TILES), 256, GEMM_SMEM>>>(
        xh, wt + O_DOWN, down_b, nullptr, xi, MT, DIN_, DIM_, 0);
    rmsnorm_kernel<<<MT, 128>>>(xi, n1w, xih, DIN_);

    // 2. pack (fp16)
    pack_kernel<<<(PACK8 + 255) / 256, 256>>>(xih, x1p, 0,    5);
    pack_kernel<<<(PACK8 + 255) / 256, 256>>>(xih, x2p, DBR_, 10);

    // 3. QKV (fp32 out for attention math)
    mma_gemm<<<dim3(768/GBN, MP_TILES), 256, GEMM_SMEM>>>(
        x1p, wt + O_QKV1, qkv1_b, nullptr, qk1, MP, 768, DBR_, 0);
    mma_gemm<<<dim3(768/GBN, MP_TILES), 256, GEMM_SMEM>>>(
        x2p, wt + O_QKV2, qkv2_b, nullptr, qk2, MP, 768, DBR_, 0);

    // 4. attention (fp16 out)
    attn_kernel<<<B_ * NW1_ * HBR_ / 4, 128>>>(qk1, ao1, rpb1, 10, NW1_, 5);
    attn_kernel<<<B_ * NW2_ * HBR_ / 4, 128>>>(qk2, ao2, rpb2, 20, NW2_, 10);

    // 5. proj (fp16 out)
    mma_gemm<<<dim3(DBR_/GBN, MP_TILES), 256, GEMM_SMEM>>>(
        ao1, wt + O_PROJ1, proj1_b, nullptr, po1, MP, DBR_, DBR_, 3);
    mma_gemm<<<dim3(DBR_/GBN, MP_TILES), 256, GEMM_SMEM>>>(
        ao2, wt + O_PROJ2, proj2_b, nullptr, po2, MP, DBR_, DBR_, 3);

    // 6. unshift + concat (fp16)
    unshift_kernel<<<(PACK8 + 255) / 256, 256>>>(po1, xcat, 0,    5);
    unshift_kernel<<<(PACK8 + 255) / 256, 256>>>(po2, xcat, DBR_, 10);

    // 7. up + residual (fp32 out)
    mma_gemm<<<dim3(DIM_/GBN, MT_TILES), 256, GEMM_SMEM>>>(
        xcat, wt + O_UP, up_b, x, xmid, MT, DIM_, DIN_, 2);

    // 8. rmsnorm2 (fp16 out)
    rmsnorm_kernel<<<MT, 256>>>(xmid, n2w, hbuf, DIM_);

    // 9. FFN1 + GELU (fp16 out)
    mma_gemm<<<dim3(2*DIM_/GBN, MT_TILES), 256, GEMM_SMEM>>>(
        hbuf, wt + O_FFN1, ffn_b1, nullptr, ffn, MT, 2*DIM_, DIM_, 1);

    // 10. FFN2 + residual -> out (fp32)
    mma_gemm<<<dim3(DIM_/GBN, MT_TILES), 256, GEMM_SMEM>>>(
        ffn, wt + O_FFN2, ffn_b2, xmid, out, MT, DIM_, 2*DIM_, 2);
}

// round 10
// speedup vs baseline: 1.7004x; 1.1433x over previous
#include <cuda_runtime.h>
#include <cuda_fp16.h>
#include <math.h>
#include <stdint.h>

// ---------------- problem constants ----------------
#define B_    8
#define T_    4096
#define DIM_  1024
#define DIN_  512
#define DBR_  256
#define HBR_  8
#define TP_   4100      // padded length (-4096 % 10 == -4096 % 20 == 4)
#define NW1_  410
#define NW2_  205

// ---------------- device scratch (static) ----------------
__device__ __half g_xh  [B_*T_*DIM_];       // fp16 copy of input x
__device__ float  g_xi  [B_*T_*DIN_];       // down output (fp32)
__device__ __half g_xih [B_*T_*DIN_];       // rmsnorm1 out (fp16)
__device__ __half g_x1p [B_*TP_*DBR_];
__device__ __half g_x2p [B_*TP_*DBR_];
__device__ __half g_qkv1[B_*TP_*3*DBR_];
__device__ __half g_qkv2[B_*TP_*3*DBR_];
__device__ __half g_ao1 [B_*TP_*DBR_];
__device__ __half g_ao2 [B_*TP_*DBR_];
__device__ __half g_po1 [B_*TP_*DBR_];
__device__ __half g_po2 [B_*TP_*DBR_];
__device__ __half g_xcat[B_*T_*DIN_];
__device__ float  g_xmid[B_*T_*DIM_];
__device__ __half g_h   [B_*T_*DIM_];       // rmsnorm2 out (fp16)
__device__ __half g_ffn [B_*T_*2*DIM_];     // gelu(ffn1) (fp16)
__device__ __half g_wt  [5767168];          // transposed (K-major) fp16 weights

// offsets (elements) into g_wt
#define O_DOWN  0u
#define O_UP    524288u
#define O_QKV1  1048576u
#define O_QKV2  1245184u
#define O_PROJ1 1441792u
#define O_PROJ2 1507328u
#define O_FFN1  1572864u
#define O_FFN2  3670016u

// ---------------- PTX helpers (base ISA only) ----------
__device__ __forceinline__ uint32_t smem_u32(const void* p) {
    uint32_t a;
    asm("{ .reg .u64 t; cvta.to.shared.u64 t, %1; cvt.u32.u64 %0, t; }" : "=r"(a) : "l"(p));
    return a;
}
__device__ __forceinline__ uint32_t h2pack(float lo, float hi) {
    __half2 h = __floats2half2_rn(lo, hi);
    return *reinterpret_cast<uint32_t*>(&h);
}
__device__ __forceinline__ void mma_f16(float* d, const uint32_t* a, const uint32_t* b) {
    asm volatile(
        "mma.sync.aligned.m16n8k16.row.col.f32.f16.f16.f32 "
        "{%0,%1,%2,%3}, {%4,%5,%6,%7}, {%8,%9}, {%0,%1,%2,%3};"
        : "+f"(d[0]), "+f"(d[1]), "+f"(d[2]), "+f"(d[3])
        : "r"(a[0]), "r"(a[1]), "r"(a[2]), "r"(a[3]), "r"(b[0]), "r"(b[1]));
}
__device__ __forceinline__ void ldsm_x4(uint32_t* r, uint32_t addr) {
    asm volatile("ldmatrix.sync.aligned.m8n8.x4.shared.b16 {%0,%1,%2,%3}, [%4];"
                 : "=r"(r[0]), "=r"(r[1]), "=r"(r[2]), "=r"(r[3]) : "r"(addr));
}
__device__ __forceinline__ void cp_async16(uint32_t dst, const void* src, int szBytes) {
    asm volatile("cp.async.cg.shared.global [%0], [%1], 16, %2;"
                 :: "r"(dst), "l"(src), "r"(szBytes));
}
__device__ __forceinline__ void cp_async16f(uint32_t dst, const void* src) {
    asm volatile("cp.async.cg.shared.global [%0], [%1], 16;"
                 :: "r"(dst), "l"(src));
}
__device__ __forceinline__ void cp_commit() { asm volatile("cp.async.commit_group;" ::: "memory"); }
__device__ __forceinline__ void cp_wait1()  { asm volatile("cp.async.wait_group 1;" ::: "memory"); }
__device__ __forceinline__ void cp_wait0()  { asm volatile("cp.async.wait_group 0;" ::: "memory"); }

// ---------------- fp16-storage warp-mma GEMM (fp32 accumulate) ----------------
// C[M,N] = A[M,K] @ Wt[N,K]^T + bias    (A, Wt fp16; ldmatrix fragments)
// mode 0: bias, fp32 out   mode 1: bias+GELU, fp16 out
// mode 2: bias+res, fp32 out   mode 3: bias, fp16 out
// CTA tile 128x256, 8 warps (2x4), warp tile 64x64, K-chunk 64, 3-stage cp.async,
// single barrier per chunk. Requires N % 256 == 0, K % 64 == 0. M guarded.
#define GBM 128
#define GBN 256
#define GBK 64
#define ASTH 72                                 // halves per row stride (144B, conflict-free)
#define STAGE_H ((GBM + GBN) * ASTH)            // 27648 halves = 55296 B
#define GEMM_SMEM (3 * STAGE_H * 2)             // 165888 bytes

__device__ __forceinline__ void stage_loads(
    const __half* __restrict__ A, const __half* __restrict__ Wt,
    int M, int K, int rowBase, int colBase, int k0,
    uint32_t asBase, uint32_t bsBase, int tid)
{
    // A: 128 rows x 8 chunks(16B = 8 halves) = 1024 slots
    #pragma unroll
    for (int i = 0; i < 4; i++) {
        int idx = tid + i * 256;
        int r = idx >> 3, c = (idx & 7) << 3;   // c in halves (0..56)
        int gr = rowBase + r;
        int sz = (gr < M) ? 16 : 0;
        if (gr >= M) gr = M - 1;
        cp_async16(asBase + (uint32_t)(r * ASTH + c) * 2u,
                   A + (size_t)gr * K + k0 + c, sz);
    }
    // B: 256 rows x 8 chunks = 2048 slots
    #pragma unroll
    for (int i = 0; i < 8; i++) {
        int idx = tid + i * 256;
        int r = idx >> 3, c = (idx & 7) << 3;
        cp_async16f(bsBase + (uint32_t)(r * ASTH + c) * 2u,
                    Wt + (size_t)(colBase + r) * K + k0 + c);
    }
    cp_commit();
}

__global__ __launch_bounds__(256, 1)
void mma_gemm(const __half* __restrict__ A, const __half* __restrict__ Wt,
              const float* __restrict__ bias, const float* __restrict__ res,
              void* __restrict__ Cv, int M, int N, int K, int mode)
{
    extern __shared__ __half smh[];
    const uint32_t smBase = smem_u32(smh);

    const int tid  = threadIdx.x;
    const int wid  = tid >> 5;
    const int lane = tid & 31;
    const int g    = lane >> 2;
    const int tg   = lane & 3;
    const int warpRow = wid >> 2;     // 0..1
    const int warpCol = wid & 3;      // 0..3
    const int rowBase = blockIdx.y * GBM;
    const int colBase = blockIdx.x * GBN;

    float acc[4][8][4];
    #pragma unroll
    for (int mt = 0; mt < 4; mt++)
        #pragma unroll
        for (int nt = 0; nt < 8; nt++)
            #pragma unroll
            for (int i = 0; i < 4; i++) acc[mt][nt][i] = 0.f;

    const int nk = K >> 6;            // K / 64
    stage_loads(A, Wt, M, K, rowBase, colBase, 0,
                smBase, smBase + GBM * ASTH * 2u, tid);
    if (nk > 1) {
        const uint32_t b1 = smBase + (uint32_t)STAGE_H * 2u;
        stage_loads(A, Wt, M, K, rowBase, colBase, GBK,
                    b1, b1 + GBM * ASTH * 2u, tid);
    }

    const uint32_t aLaneOff = (uint32_t)((warpRow * 64 + (lane & 15)) * ASTH + (lane >> 4) * 8) * 2u;
    const uint32_t bLaneOff = (uint32_t)((warpCol * 64 + (lane & 7) + ((lane >> 4) << 3)) * ASTH
                                         + ((lane >> 3) & 1) * 8) * 2u;

    for (int kc = 0; kc < nk; kc++) {
        const int s = kc % 3;
        if (kc + 1 < nk) cp_wait1(); else cp_wait0();
        __syncthreads();
        // issue loads for stage kc+2 AFTER the barrier: its target buffer
        // ((kc+2)%3 == (kc-1)%3) was last read in iteration kc-1, which every
        // warp finished before this barrier.
        if (kc + 2 < nk) {
            const uint32_t nb = smBase + (uint32_t)(((kc + 2) % 3) * STAGE_H) * 2u;
            stage_loads(A, Wt, M, K, rowBase, colBase, (kc + 2) * GBK,
                        nb, nb + GBM * ASTH * 2u, tid);
        }

        const uint32_t aBase = smBase + (uint32_t)(s * STAGE_H) * 2u + aLaneOff;
        const uint32_t bBase = smBase + (uint32_t)(s * STAGE_H + GBM * ASTH) * 2u + bLaneOff;

        #pragma unroll
        for (int ks = 0; ks < 4; ks++) {
            const uint32_t ko = (uint32_t)ks * 32u;   // 16 halves = 32 bytes
            uint32_t afr[4][4], bfr[8][2];
            #pragma unroll
            for (int mt = 0; mt < 4; mt++)
                ldsm_x4(afr[mt], aBase + (uint32_t)(mt * 16 * ASTH) * 2u + ko);
            #pragma unroll
            for (int ntp = 0; ntp < 4; ntp++) {
                uint32_t q[4];
                ldsm_x4(q, bBase + (uint32_t)(ntp * 16 * ASTH) * 2u + ko);
                bfr[2 * ntp + 0][0] = q[0]; bfr[2 * ntp + 0][1] = q[1];
                bfr[2 * ntp + 1][0] = q[2]; bfr[2 * ntp + 1][1] = q[3];
            }
            #pragma unroll
            for (int mt = 0; mt < 4; mt++)
                #pragma unroll
                for (int nt = 0; nt < 8; nt++)
                    mma_f16(acc[mt][nt], afr[mt], bfr[nt]);
        }
    }

    // ---------------- epilogue ----------------
    float* Cf = (float*)Cv;
    __half* Ch = (__half*)Cv;
    #pragma unroll
    for (int mt = 0; mt < 4; mt++) {
        #pragma unroll
        for (int nt = 0; nt < 8; nt++) {
            const int r0 = rowBase + warpRow * 64 + mt * 16 + g;
            const int cc = colBase + warpCol * 64 + nt * 8 + 2 * tg;
            const float bx = bias[cc], by = bias[cc + 1];
            #pragma unroll
            for (int h = 0; h < 2; h++) {
                const int row = r0 + h * 8;
                if (row >= M) continue;
                float v0 = acc[mt][nt][2 * h + 0] + bx;
                float v1 = acc[mt][nt][2 * h + 1] + by;
                if (mode == 1) {
                    v0 = 0.5f * v0 * (1.0f + erff(v0 * 0.70710678118654752f));
                    v1 = 0.5f * v1 * (1.0f + erff(v1 * 0.70710678118654752f));
                    *(__half2*)(Ch + (size_t)row * N + cc) = __floats2half2_rn(v0, v1);
                } else if (mode == 3) {
                    *(__half2*)(Ch + (size_t)row * N + cc) = __floats2half2_rn(v0, v1);
                } else {
                    if (mode == 2) {
                        const float2 rv = *(const float2*)(res + (size_t)row * N + cc);
                        v0 += rv.x; v1 += rv.y;
                    }
                    *(float2*)(Cf + (size_t)row * N + cc) = make_float2(v0, v1);
                }
            }
        }
    }
}

// ---------------- weight transpose: src[K,N] fp32 -> dst[N,K] fp16 ----------------
__global__ void transpose_kernel(const float* __restrict__ src, __half* __restrict__ dst,
                                 int K, int N)
{
    __shared__ float t[32][33];
    const int kb = blockIdx.y * 32, nb = blockIdx.x * 32;
    const int x = threadIdx.x, y = threadIdx.y;
    #pragma unroll
    for (int i = 0; i < 32; i += 8)
        t[y + i][x] = src[(size_t)(kb + y + i) * N + nb + x];
    __syncthreads();
    #pragma unroll
    for (int i = 0; i < 32; i += 8)
        dst[(size_t)(nb + y + i) * K + kb + x] = __float2half(t[x][y + i]);
}

// ---------------- fp32 -> fp16 convert ----------------
__global__ void f2h_kernel(const float* __restrict__ in, __half* __restrict__ out, int n8)
{
    int idx = blockIdx.x * blockDim.x + threadIdx.x;
    if (idx >= n8) return;
    const float4* p = (const float4*)(in + (size_t)idx * 8);
    float4 a = p[0], b = p[1];
    uint4 u;
    u.x = h2pack(a.x, a.y); u.y = h2pack(a.z, a.w);
    u.z = h2pack(b.x, b.y); u.w = h2pack(b.z, b.w);
    *(uint4*)(out + (size_t)idx * 8) = u;
}

// ---------------- RMSNorm: fp32 in, fp16 out ----------------
__global__ void rmsnorm_kernel(const float* __restrict__ in, const float* __restrict__ w,
                               __half* __restrict__ out, int C)
{
    const int row = blockIdx.x;
    const float4* p4 = (const float4*)(in + (size_t)row * C);
    const float4* w4 = (const float4*)w;
    const int C4 = C >> 2;
    float s = 0.f;
    for (int c = threadIdx.x; c < C4; c += blockDim.x) {
        float4 v = p4[c];
        s += v.x * v.x + v.y * v.y + v.z * v.z + v.w * v.w;
    }
    #pragma unroll
    for (int o = 16; o > 0; o >>= 1) s += __shfl_xor_sync(0xffffffffu, s, o);
    __shared__ float red[8];
    __shared__ float scale;
    int wid = threadIdx.x >> 5, lane = threadIdx.x & 31;
    if (lane == 0) red[wid] = s;
    __syncthreads();
    if (threadIdx.x == 0) {
        float t = 0.f;
        for (int i = 0; i < (int)(blockDim.x >> 5); i++) t += red[i];
        scale = rsqrtf(t / (float)C + 1e-6f);
    }
    __syncthreads();
    float sc = scale;
    for (int c = threadIdx.x; c < C4; c += blockDim.x) {
        float4 v = p4[c], ww = w4[c];
        uint2 u;
        u.x = h2pack(v.x * sc * ww.x, v.y * sc * ww.y);
        u.y = h2pack(v.z * sc * ww.z, v.w * sc * ww.w);
        *(uint2*)(out + (size_t)row * C + c * 4) = u;
    }
}

// ---------------- pad + roll(-shift) + split (fp16, 16B) ----------------
__global__ void pack_kernel(const __half* __restrict__ xi, __half* __restrict__ xp,
                            int off, int shift)
{
    int idx = blockIdx.x * blockDim.x + threadIdx.x;
    const int total = B_ * TP_ * (DBR_ / 8);
    if (idx >= total) return;
    int c = (idx & 31) << 3;
    int t = (idx >> 5) % TP_;
    int b = idx / (32 * TP_);
    int ts = t + shift; if (ts >= TP_) ts -= TP_;
    uint4 v = make_uint4(0u, 0u, 0u, 0u);
    if (ts < T_) v = *(const uint4*)(xi + ((size_t)b * T_ + ts) * DIN_ + off + c);
    *(uint4*)(xp + (size_t)idx * 8) = v;
}

// ---------------- roll(+shift), truncate, concat (fp16, 16B) ----------------
__global__ void unshift_kernel(const __half* __restrict__ po, __half* __restrict__ xcat,
                               int off, int shift)
{
    int idx = blockIdx.x * blockDim.x + threadIdx.x;
    const int total = B_ * TP_ * (DBR_ / 8);
    if (idx >= total) return;
    int c = (idx & 31) << 3;
    int r = (idx >> 5) % TP_;
    int b = idx / (32 * TP_);
    int t = r + shift; if (t >= TP_) t -= TP_;
    if (t < T_) {
        uint4 v = *(const uint4*)(po + (size_t)idx * 8);
        *(uint4*)(xcat + ((size_t)b * T_ + t) * DIN_ + off + c) = v;
    }
}

// ---------------- windowed attention (warp per b,window,head); fp16 in/out ----------
#define ATT_SLICE 2336
__global__ __launch_bounds__(128)
void attn_kernel(const __half* __restrict__ qkv, __half* __restrict__ ao,
                 const float* __restrict__ rpb, int w, int nW, int shift)
{
    __shared__ float sm[4 * ATT_SLICE];
    const int warp = threadIdx.x >> 5, lane = threadIdx.x & 31;
    float* S = sm + warp * ATT_SLICE;
    const int gw = blockIdx.x * 4 + warp;
    const int h = gw & 7;
    const int n = (gw >> 3) % nW;
    const int b = gw / (8 * nW);

    float* q  = S;
    float* k  = S + w * 32;
    float* v  = S + 2 * w * 32;
    float* lg = S + 3 * w * 32;

    const size_t rbase = (size_t)b * TP_ + (size_t)n * w;
    for (int i = 0; i < w; i++) {
        size_t ro = (rbase + i) * 768 + h * 32 + lane;
        q[i * 32 + lane] = __half2float(qkv[ro]);
        k[i * 32 + lane] = __half2float(qkv[ro + 256]);
        v[i * 32 + lane] = __half2float(qkv[ro + 512]);
    }
    __syncwarp();

    const float scale = 0.17677669529663687f;
    const bool lastwin = (n == nW - 1);
    for (int p = lane; p < w * w; p += 32) {
        int i = p / w, j = p % w;
        float s = 0.f;
        #pragma unroll
        for (int d = 0; d < 32; d++) s = fmaf(q[i * 32 + d], k[j * 32 + d], s);
        s *= scale;
        s += rpb[(i - j + w - 1) * 8 + h];
        if (lastwin) {
            int mi = (i >= w - shift) ? 2 : 1;
            int mj = (j >= w - shift) ? 2 : 1;
            if (mi != mj) s -= 100.f;
        }
        lg[p] = s;
    }
    __syncwarp();

    if (lane < w) {
        float mx = -3.0e38f;
        for (int j = 0; j < w; j++) mx = fmaxf(mx, lg[lane * w + j]);
        float sum = 0.f;
        for (int j = 0; j < w; j++) { float e = expf(lg[lane * w + j] - mx); lg[lane * w + j] = e; sum += e; }
        float inv = 1.f / sum;
        for (int j = 0; j < w; j++) lg[lane * w + j] *= inv;
    }
    __syncwarp();

    for (int i = 0; i < w; i++) {
        float a = 0.f;
        for (int j = 0; j < w; j++) a = fmaf(lg[i * w + j], v[j * 32 + lane], a);
        ao[(rbase + i) * 256 + h * 32 + lane] = __float2half(a);
    }
}

// ---------------- launch ----------------
extern "C" void kernel_launch(void* const* d_in, const int* in_sizes, int n_in,
                              void* d_out, int out_size)
{
    (void)in_sizes; (void)n_in; (void)out_size;
    const float* x       = (const float*)d_in[0];
    const float* down_w  = (const float*)d_in[1];
    const float* down_b  = (const float*)d_in[2];
    const float* up_w    = (const float*)d_in[3];
    const float* up_b    = (const float*)d_in[4];
    const float* n1w     = (const float*)d_in[5];
    const float* n2w     = (const float*)d_in[6];
    const float* qkv1_w  = (const float*)d_in[7];
    const float* qkv1_b  = (const float*)d_in[8];
    const float* proj1_w = (const float*)d_in[9];
    const float* proj1_b = (const float*)d_in[10];
    const float* rpb1    = (const float*)d_in[11];
    const float* qkv2_w  = (const float*)d_in[12];
    const float* qkv2_b  = (const float*)d_in[13];
    const float* proj2_w = (const float*)d_in[14];
    const float* proj2_b = (const float*)d_in[15];
    const float* rpb2    = (const float*)d_in[16];
    const float* ffn_w1  = (const float*)d_in[17];
    const float* ffn_b1  = (const float*)d_in[18];
    const float* ffn_w2  = (const float*)d_in[19];
    const float* ffn_b2  = (const float*)d_in[20];
    float* out = (float*)d_out;

    __half *xh, *xih, *x1p, *x2p, *qk1, *qk2, *ao1, *ao2, *po1, *po2, *xcat, *hbuf, *ffn, *wt;
    float *xi, *xmid;
    cudaGetSymbolAddress((void**)&xh,   g_xh);
    cudaGetSymbolAddress((void**)&xi,   g_xi);
    cudaGetSymbolAddress((void**)&xih,  g_xih);
    cudaGetSymbolAddress((void**)&x1p,  g_x1p);
    cudaGetSymbolAddress((void**)&x2p,  g_x2p);
    cudaGetSymbolAddress((void**)&qk1,  g_qkv1);
    cudaGetSymbolAddress((void**)&qk2,  g_qkv2);
    cudaGetSymbolAddress((void**)&ao1,  g_ao1);
    cudaGetSymbolAddress((void**)&ao2,  g_ao2);
    cudaGetSymbolAddress((void**)&po1,  g_po1);
    cudaGetSymbolAddress((void**)&po2,  g_po2);
    cudaGetSymbolAddress((void**)&xcat, g_xcat);
    cudaGetSymbolAddress((void**)&xmid, g_xmid);
    cudaGetSymbolAddress((void**)&hbuf, g_h);
    cudaGetSymbolAddress((void**)&ffn,  g_ffn);
    cudaGetSymbolAddress((void**)&wt,   g_wt);

    cudaFuncSetAttribute(mma_gemm, cudaFuncAttributeMaxDynamicSharedMemorySize, GEMM_SMEM);

    const int MT = B_ * T_;    // 32768
    const int MP = B_ * TP_;   // 32800
    const int PACK8 = B_ * TP_ * (DBR_ / 8);
    const int MT_TILES = MT / GBM;              // 256
    const int MP_TILES = (MP + GBM - 1) / GBM;  // 257

    // 0. transpose weights to K-major fp16 + convert x to fp16
    transpose_kernel<<<dim3(DIN_/32,  DIM_/32),   dim3(32,8)>>>(down_w,  wt + O_DOWN,  DIM_,  DIN_);
    transpose_kernel<<<dim3(DIM_/32,  DIN_/32),   dim3(32,8)>>>(up_w,    wt + O_UP,    DIN_,  DIM_);
    transpose_kernel<<<dim3(768/32,   DBR_/32),   dim3(32,8)>>>(qkv1_w,  wt + O_QKV1,  DBR_,  768);
    transpose_kernel<<<dim3(768/32,   DBR_/32),   dim3(32,8)>>>(qkv2_w,  wt + O_QKV2,  DBR_,  768);
    transpose_kernel<<<dim3(DBR_/32,  DBR_/32),   dim3(32,8)>>>(proj1_w, wt + O_PROJ1, DBR_,  DBR_);
    transpose_kernel<<<dim3(DBR_/32,  DBR_/32),   dim3(32,8)>>>(proj2_w, wt + O_PROJ2, DBR_,  DBR_);
    transpose_kernel<<<dim3(2*DIM_/32, DIM_/32),  dim3(32,8)>>>(ffn_w1,  wt + O_FFN1,  DIM_,  2*DIM_);
    transpose_kernel<<<dim3(DIM_/32,  2*DIM_/32), dim3(32,8)>>>(ffn_w2,  wt + O_FFN2,  2*DIM_, DIM_);
    f2h_kernel<<<(MT * DIM_ / 8 + 255) / 256, 256>>>(x, xh, MT * DIM_ / 8);

    // 1. down + rmsnorm1 (fp16 out)
    mma_gemm<<<dim3(DIN_/GBN, MT_TILES), 256, GEMM_SMEM>>>(
        xh, wt + O_DOWN, down_b, nullptr, xi, MT, DIN_, DIM_, 0);
    rmsnorm_kernel<<<MT, 128>>>(xi, n1w, xih, DIN_);

    // 2. pack (fp16)
    pack_kernel<<<(PACK8 + 255) / 256, 256>>>(xih, x1p, 0,    5);
    pack_kernel<<<(PACK8 + 255) / 256, 256>>>(xih, x2p, DBR_, 10);

    // 3. QKV (fp16 out)
    mma_gemm<<<dim3(768/GBN, MP_TILES), 256, GEMM_SMEM>>>(
        x1p, wt + O_QKV1, qkv1_b, nullptr, qk1, MP, 768, DBR_, 3);
    mma_gemm<<<dim3(768/GBN, MP_TILES), 256, GEMM_SMEM>>>(
        x2p, wt + O_QKV2, qkv2_b, nullptr, qk2, MP, 768, DBR_, 3);

    // 4. attention (fp16 in/out)
    attn_kernel<<<B_ * NW1_ * HBR_ / 4, 128>>>(qk1, ao1, rpb1, 10, NW1_, 5);
    attn_kernel<<<B_ * NW2_ * HBR_ / 4, 128>>>(qk2, ao2, rpb2, 20, NW2_, 10);

    // 5. proj (fp16 out)
    mma_gemm<<<dim3(DBR_/GBN, MP_TILES), 256, GEMM_SMEM>>>(
        ao1, wt + O_PROJ1, proj1_b, nullptr, po1, MP, DBR_, DBR_, 3);
    mma_gemm<<<dim3(DBR_/GBN, MP_TILES), 256, GEMM_SMEM>>>(
        ao2, wt + O_PROJ2, proj2_b, nullptr, po2, MP, DBR_, DBR_, 3);

    // 6. unshift + concat (fp16)
    unshift_kernel<<<(PACK8 + 255) / 256, 256>>>(po1, xcat, 0,    5);
    unshift_kernel<<<(PACK8 + 255) / 256, 256>>>(po2, xcat, DBR_, 10);

    // 7. up + residual (fp32 out)
    mma_gemm<<<dim3(DIM_/GBN, MT_TILES), 256, GEMM_SMEM>>>(
        xcat, wt + O_UP, up_b, x, xmid, MT, DIM_, DIN_, 2);

    // 8. rmsnorm2 (fp16 out)
    rmsnorm_kernel<<<MT, 256>>>(xmid, n2w, hbuf, DIM_);

    // 9. FFN1 + GELU (fp16 out)
    mma_gemm<<<dim3(2*DIM_/GBN, MT_TILES), 256, GEMM_SMEM>>>(
        hbuf, wt + O_FFN1, ffn_b1, nullptr, ffn, MT, 2*DIM_, DIM_, 1);

    // 10. FFN2 + residual -> out (fp32)
    mma_gemm<<<dim3(DIM_/GBN, MT_TILES), 256, GEMM_SMEM>>>(
        ffn, wt + O_FFN2, ffn_b2, xmid, out, MT, DIM_, 2*DIM_, 2);
}

// round 11
// speedup vs baseline: 1.7773x; 1.0452x over previous
#include <cuda_runtime.h>
#include <cuda_fp16.h>
#include <math.h>
#include <stdint.h>

// ---------------- problem constants ----------------
#define B_    8
#define T_    4096
#define DIM_  1024
#define DIN_  512
#define DBR_  256
#define HBR_  8
#define TP_   4100
#define NW1_  410
#define NW2_  205

// ---------------- device scratch (static) ----------------
__device__ __half g_xh  [B_*T_*DIM_];
__device__ float  g_xi  [B_*T_*DIN_];
__device__ __half g_xih [B_*T_*DIN_];
__device__ __half g_qkv1[B_*TP_*3*DBR_];
__device__ __half g_qkv2[B_*TP_*3*DBR_];
__device__ __half g_ao1 [B_*TP_*DBR_];
__device__ __half g_ao2 [B_*TP_*DBR_];
__device__ __half g_xcat[B_*T_*DIN_];
__device__ float  g_xmid[B_*T_*DIM_];
__device__ __half g_h   [B_*T_*DIM_];
__device__ __half g_ffn [B_*T_*2*DIM_];
__device__ __half g_wt  [5767168];

#define O_DOWN  0u
#define O_UP    524288u
#define O_QKV1  1048576u
#define O_QKV2  1245184u
#define O_PROJ1 1441792u
#define O_PROJ2 1507328u
#define O_FFN1  1572864u
#define O_FFN2  3670016u

// ---------------- PTX helpers ----------
__device__ __forceinline__ uint32_t smem_u32(const void* p) {
    uint32_t a;
    asm("{ .reg .u64 t; cvta.to.shared.u64 t, %1; cvt.u32.u64 %0, t; }" : "=r"(a) : "l"(p));
    return a;
}
__device__ __forceinline__ uint32_t h2pack(float lo, float hi) {
    __half2 h = __floats2half2_rn(lo, hi);
    return *reinterpret_cast<uint32_t*>(&h);
}
__device__ __forceinline__ void mma_f16(float* d, const uint32_t* a, const uint32_t* b) {
    asm volatile(
        "mma.sync.aligned.m16n8k16.row.col.f32.f16.f16.f32 "
        "{%0,%1,%2,%3}, {%4,%5,%6,%7}, {%8,%9}, {%0,%1,%2,%3};"
        : "+f"(d[0]), "+f"(d[1]), "+f"(d[2]), "+f"(d[3])
        : "r"(a[0]), "r"(a[1]), "r"(a[2]), "r"(a[3]), "r"(b[0]), "r"(b[1]));
}
__device__ __forceinline__ void ldsm_x4(uint32_t* r, uint32_t addr) {
    asm volatile("ldmatrix.sync.aligned.m8n8.x4.shared.b16 {%0,%1,%2,%3}, [%4];"
                 : "=r"(r[0]), "=r"(r[1]), "=r"(r[2]), "=r"(r[3]) : "r"(addr));
}
__device__ __forceinline__ void cp_async16(uint32_t dst, const void* src, int szBytes) {
    asm volatile("cp.async.cg.shared.global [%0], [%1], 16, %2;"
                 :: "r"(dst), "l"(src), "r"(szBytes));
}
__device__ __forceinline__ void cp_async16f(uint32_t dst, const void* src) {
    asm volatile("cp.async.cg.shared.global [%0], [%1], 16;"
                 :: "r"(dst), "l"(src));
}
__device__ __forceinline__ void cp_commit() { asm volatile("cp.async.commit_group;" ::: "memory"); }
__device__ __forceinline__ void cp_wait1()  { asm volatile("cp.async.wait_group 1;" ::: "memory"); }
__device__ __forceinline__ void cp_wait0()  { asm volatile("cp.async.wait_group 0;" ::: "memory"); }

// ---------------- fp16-storage warp-mma GEMM (fp32 accumulate) ----------------
// C[M,N] = A[M,K] @ Wt[N,K]^T + bias
// mode 0: bias, fp32 out           mode 1: bias+GELU, fp16 out
// mode 2: bias+res, fp32 out       mode 3: bias, fp16 out
// mode 4: bias, fp16 out with unshift row-remap into [B*T, DIN] at col oColOff
// aPack: A rows gathered from [B*T_, DIN_] via roll(+aShift)+pad, col offset aColOff
#define GBM 128
#define GBN 256
#define GBK 64
#define ASTH 72
#define STAGE_H ((GBM + GBN) * ASTH)
#define GEMM_SMEM (3 * STAGE_H * 2)             // 165888 bytes

__device__ __forceinline__ void stage_loads(
    const __half* __restrict__ A, const __half* __restrict__ Wt,
    int M, int K, int rowBase, int colBase, int k0,
    uint32_t asBase, uint32_t bsBase, int tid,
    int aPack, int aShift, int aColOff)
{
    #pragma unroll
    for (int i = 0; i < 4; i++) {
        int idx = tid + i * 256;
        int r = idx >> 3, c = (idx & 7) << 3;
        int gr = rowBase + r;
        const __half* src;
        int sz;
        if (aPack) {
            int b = gr / TP_;
            int t = gr - b * TP_;
            int ts = t + aShift; if (ts >= TP_) ts -= TP_;
            sz = (gr < M && ts < T_) ? 16 : 0;
            if (ts >= T_) ts = 0;
            if (b >= B_) b = B_ - 1;
            src = A + ((size_t)b * T_ + ts) * DIN_ + aColOff + k0 + c;
        } else {
            sz = (gr < M) ? 16 : 0;
            if (gr >= M) gr = M - 1;
            src = A + (size_t)gr * K + k0 + c;
        }
        cp_async16(asBase + (uint32_t)(r * ASTH + c) * 2u, src, sz);
    }
    #pragma unroll
    for (int i = 0; i < 8; i++) {
        int idx = tid + i * 256;
        int r = idx >> 3, c = (idx & 7) << 3;
        cp_async16f(bsBase + (uint32_t)(r * ASTH + c) * 2u,
                    Wt + (size_t)(colBase + r) * K + k0 + c);
    }
    cp_commit();
}

__global__ __launch_bounds__(256, 1)
void mma_gemm(const __half* __restrict__ A, const __half* __restrict__ Wt,
              const float* __restrict__ bias, const float* __restrict__ res,
              void* __restrict__ Cv, int M, int N, int K, int mode,
              int aPack, int aShift, int aColOff, int oShift, int oColOff)
{
    extern __shared__ __half smh[];
    const uint32_t smBase = smem_u32(smh);

    const int tid  = threadIdx.x;
    const int wid  = tid >> 5;
    const int lane = tid & 31;
    const int g    = lane >> 2;
    const int tg   = lane & 3;
    const int warpRow = wid >> 2;
    const int warpCol = wid & 3;
    const int rowBase = blockIdx.y * GBM;
    const int colBase = blockIdx.x * GBN;

    float acc[4][8][4];
    #pragma unroll
    for (int mt = 0; mt < 4; mt++)
        #pragma unroll
        for (int nt = 0; nt < 8; nt++)
            #pragma unroll
            for (int i = 0; i < 4; i++) acc[mt][nt][i] = 0.f;

    const int nk = K >> 6;
    stage_loads(A, Wt, M, K, rowBase, colBase, 0,
                smBase, smBase + GBM * ASTH * 2u, tid, aPack, aShift, aColOff);
    if (nk > 1) {
        const uint32_t b1 = smBase + (uint32_t)STAGE_H * 2u;
        stage_loads(A, Wt, M, K, rowBase, colBase, GBK,
                    b1, b1 + GBM * ASTH * 2u, tid, aPack, aShift, aColOff);
    }

    const uint32_t aLaneOff = (uint32_t)((warpRow * 64 + (lane & 15)) * ASTH + (lane >> 4) * 8) * 2u;
    const uint32_t bLaneOff = (uint32_t)((warpCol * 64 + (lane & 7) + ((lane >> 4) << 3)) * ASTH
                                         + ((lane >> 3) & 1) * 8) * 2u;

    for (int kc = 0; kc < nk; kc++) {
        const int s = kc % 3;
        if (kc + 1 < nk) cp_wait1(); else cp_wait0();
        __syncthreads();
        if (kc + 2 < nk) {
            const uint32_t nb = smBase + (uint32_t)(((kc + 2) % 3) * STAGE_H) * 2u;
            stage_loads(A, Wt, M, K, rowBase, colBase, (kc + 2) * GBK,
                        nb, nb + GBM * ASTH * 2u, tid, aPack, aShift, aColOff);
        }

        const uint32_t aBase = smBase + (uint32_t)(s * STAGE_H) * 2u + aLaneOff;
        const uint32_t bBase = smBase + (uint32_t)(s * STAGE_H + GBM * ASTH) * 2u + bLaneOff;

        #pragma unroll
        for (int ks = 0; ks < 4; ks++) {
            const uint32_t ko = (uint32_t)ks * 32u;
            uint32_t afr[4][4], bfr[8][2];
            #pragma unroll
            for (int mt = 0; mt < 4; mt++)
                ldsm_x4(afr[mt], aBase + (uint32_t)(mt * 16 * ASTH) * 2u + ko);
            #pragma unroll
            for (int ntp = 0; ntp < 4; ntp++) {
                uint32_t q[4];
                ldsm_x4(q, bBase + (uint32_t)(ntp * 16 * ASTH) * 2u + ko);
                bfr[2 * ntp + 0][0] = q[0]; bfr[2 * ntp + 0][1] = q[1];
                bfr[2 * ntp + 1][0] = q[2]; bfr[2 * ntp + 1][1] = q[3];
            }
            #pragma unroll
            for (int mt = 0; mt < 4; mt++)
                #pragma unroll
                for (int nt = 0; nt < 8; nt++)
                    mma_f16(acc[mt][nt], afr[mt], bfr[nt]);
        }
    }

    // ---------------- epilogue ----------------
    float* Cf = (float*)Cv;
    __half* Ch = (__half*)Cv;
    #pragma unroll
    for (int mt = 0; mt < 4; mt++) {
        #pragma unroll
        for (int nt = 0; nt < 8; nt++) {
            const int r0 = rowBase + warpRow * 64 + mt * 16 + g;
            const int cc = colBase + warpCol * 64 + nt * 8 + 2 * tg;
            const float bx = bias[cc], by = bias[cc + 1];
            #pragma unroll
            for (int h = 0; h < 2; h++) {
                const int row = r0 + h * 8;
                if (row >= M) continue;
                float v0 = acc[mt][nt][2 * h + 0] + bx;
                float v1 = acc[mt][nt][2 * h + 1] + by;
                if (mode == 1) {
                    v0 = 0.5f * v0 * (1.0f + erff(v0 * 0.70710678118654752f));
                    v1 = 0.5f * v1 * (1.0f + erff(v1 * 0.70710678118654752f));
                    *(__half2*)(Ch + (size_t)row * N + cc) = __floats2half2_rn(v0, v1);
                } else if (mode == 3) {
                    *(__half2*)(Ch + (size_t)row * N + cc) = __floats2half2_rn(v0, v1);
                } else if (mode == 4) {
                    int b = row / TP_;
                    int r = row - b * TP_;
                    int t = r + oShift; if (t >= TP_) t -= TP_;
                    if (t < T_)
                        *(__half2*)(Ch + ((size_t)b * T_ + t) * DIN_ + oColOff + cc) =
                            __floats2half2_rn(v0, v1);
                } else {
                    if (mode == 2) {
                        const float2 rv = *(const float2*)(res + (size_t)row * N + cc);
                        v0 += rv.x; v1 += rv.y;
                    }
                    *(float2*)(Cf + (size_t)row * N + cc) = make_float2(v0, v1);
                }
            }
        }
    }
}

// ---------------- fused prep: 8 weight transposes (fp32->fp16 K-major) + x f2h ----
struct PrepArgs {
    const float* src[8];
    uint32_t     dstOff[8];   // into g_wt
    int          K[8], N[8], tiles[8];  // tiles = (N/32)*(K/32)
    const float* x;
    int          n8;          // f2h vector count
};
#define F2H_BLOCKS 16384      // n8 / 256 = (32768*1024/8)/256

__global__ __launch_bounds__(256)
void prep_kernel(PrepArgs pa)
{
    const int tid = threadIdx.x;
    int bid = blockIdx.x;
    if (bid < F2H_BLOCKS) {
        __half* xh = g_xh;
        int idx = bid * 256 + tid;
        if (idx < pa.n8) {
            const float4* p = (const float4*)(pa.x + (size_t)idx * 8);
            float4 a = p[0], b = p[1];
            uint4 u;
            u.x = h2pack(a.x, a.y); u.y = h2pack(a.z, a.w);
            u.z = h2pack(b.x, b.y); u.w = h2pack(b.z, b.w);
            *(uint4*)(xh + (size_t)idx * 8) = u;
        }
        return;
    }
    bid -= F2H_BLOCKS;
    int e = 0;
    #pragma unroll
    for (int i = 0; i < 8; i++) {
        if (bid >= pa.tiles[i] && e == i) { bid -= pa.tiles[i]; e = i + 1; }
    }
    const float* src = pa.src[e];
    __half* dst = g_wt + pa.dstOff[e];
    const int K = pa.K[e], N = pa.N[e];
    const int tilesX = N >> 5;
    const int nb = (bid % tilesX) << 5;
    const int kb = (bid / tilesX) << 5;

    __shared__ float t[32][33];
    const int x = tid & 31, y = tid >> 5;
    #pragma unroll
    for (int i = 0; i < 32; i += 8)
        t[y + i][x] = src[(size_t)(kb + y + i) * N + nb + x];
    __syncthreads();
    #pragma unroll
    for (int i = 0; i < 32; i += 8)
        dst[(size_t)(nb + y + i) * K + kb + x] = __float2half(t[x][y + i]);
}

// ---------------- RMSNorm: fp32 in, fp16 out ----------------
__global__ void rmsnorm_kernel(const float* __restrict__ in, const float* __restrict__ w,
                               __half* __restrict__ out, int C)
{
    const int row = blockIdx.x;
    const float4* p4 = (const float4*)(in + (size_t)row * C);
    const float4* w4 = (const float4*)w;
    const int C4 = C >> 2;
    float s = 0.f;
    for (int c = threadIdx.x; c < C4; c += blockDim.x) {
        float4 v = p4[c];
        s += v.x * v.x + v.y * v.y + v.z * v.z + v.w * v.w;
    }
    #pragma unroll
    for (int o = 16; o > 0; o >>= 1) s += __shfl_xor_sync(0xffffffffu, s, o);
    __shared__ float red[8];
    __shared__ float scale;
    int wid = threadIdx.x >> 5, lane = threadIdx.x & 31;
    if (lane == 0) red[wid] = s;
    __syncthreads();
    if (threadIdx.x == 0) {
        float t = 0.f;
        for (int i = 0; i < (int)(blockDim.x >> 5); i++) t += red[i];
        scale = rsqrtf(t / (float)C + 1e-6f);
    }
    __syncthreads();
    float sc = scale;
    for (int c = threadIdx.x; c < C4; c += blockDim.x) {
        float4 v = p4[c], ww = w4[c];
        uint2 u;
        u.x = h2pack(v.x * sc * ww.x, v.y * sc * ww.y);
        u.y = h2pack(v.z * sc * ww.z, v.w * sc * ww.w);
        *(uint2*)(out + (size_t)row * C + c * 4) = u;
    }
}

// ---------------- windowed attention, templated (warp per b,window,head) ----------
template <int W, int NW, int SHIFT>
__global__ __launch_bounds__(128)
void attn_kernel(const __half* __restrict__ qkv, __half* __restrict__ ao,
                 const float* __restrict__ rpb)
{
    constexpr int SLICE = 3 * W * 32 + W * W + 8;
    __shared__ float sm[4 * SLICE];
    const int warp = threadIdx.x >> 5, lane = threadIdx.x & 31;
    float* S = sm + warp * SLICE;
    const int gw = blockIdx.x * 4 + warp;
    const int h = gw & 7;
    const int n = (gw >> 3) % NW;
    const int b = gw / (8 * NW);

    float* q  = S;
    float* k  = S + W * 32;
    float* v  = S + 2 * W * 32;
    float* lg = S + 3 * W * 32;

    const size_t rbase = (size_t)b * TP_ + (size_t)n * W;
    #pragma unroll
    for (int i = 0; i < W; i++) {
        size_t ro = (rbase + i) * 768 + h * 32 + lane;
        q[i * 32 + lane] = __half2float(qkv[ro]);
        k[i * 32 + lane] = __half2float(qkv[ro + 256]);
        v[i * 32 + lane] = __half2float(qkv[ro + 512]);
    }
    __syncwarp();

    const float scale = 0.17677669529663687f;
    const bool lastwin = (n == NW - 1);
    for (int p = lane; p < W * W; p += 32) {
        int i = p / W, j = p % W;
        float s = 0.f;
        #pragma unroll
        for (int d = 0; d < 32; d++) s = fmaf(q[i * 32 + d], k[j * 32 + d], s);
        s *= scale;
        s += rpb[(i - j + W - 1) * 8 + h];
        if (lastwin) {
            int mi = (i >= W - SHIFT) ? 2 : 1;
            int mj = (j >= W - SHIFT) ? 2 : 1;
            if (mi != mj) s -= 100.f;
        }
        lg[p] = s;
    }
    __syncwarp();

    if (lane < W) {
        float mx = -3.0e38f;
        #pragma unroll
        for (int j = 0; j < W; j++) mx = fmaxf(mx, lg[lane * W + j]);
        float sum = 0.f;
        #pragma unroll
        for (int j = 0; j < W; j++) {
            float e = __expf(lg[lane * W + j] - mx);
            lg[lane * W + j] = e; sum += e;
        }
        float inv = 1.f / sum;
        #pragma unroll
        for (int j = 0; j < W; j++) lg[lane * W + j] *= inv;
    }
    __syncwarp();

    #pragma unroll
    for (int i = 0; i < W; i++) {
        float a = 0.f;
        #pragma unroll
        for (int j = 0; j < W; j++) a = fmaf(lg[i * W + j], v[j * 32 + lane], a);
        ao[(rbase + i) * 256 + h * 32 + lane] = __float2half(a);
    }
}

// ---------------- launch ----------------
extern "C" void kernel_launch(void* const* d_in, const int* in_sizes, int n_in,
                              void* d_out, int out_size)
{
    (void)in_sizes; (void)n_in; (void)out_size;
    const float* x       = (const float*)d_in[0];
    const float* down_w  = (const float*)d_in[1];
    const float* down_b  = (const float*)d_in[2];
    const float* up_w    = (const float*)d_in[3];
    const float* up_b    = (const float*)d_in[4];
    const float* n1w     = (const float*)d_in[5];
    const float* n2w     = (const float*)d_in[6];
    const float* qkv1_w  = (const float*)d_in[7];
    const float* qkv1_b  = (const float*)d_in[8];
    const float* proj1_w = (const float*)d_in[9];
    const float* proj1_b = (const float*)d_in[10];
    const float* rpb1    = (const float*)d_in[11];
    const float* qkv2_w  = (const float*)d_in[12];
    const float* qkv2_b  = (const float*)d_in[13];
    const float* proj2_w = (const float*)d_in[14];
    const float* proj2_b = (const float*)d_in[15];
    const float* rpb2    = (const float*)d_in[16];
    const float* ffn_w1  = (const float*)d_in[17];
    const float* ffn_b1  = (const float*)d_in[18];
    const float* ffn_w2  = (const float*)d_in[19];
    const float* ffn_b2  = (const float*)d_in[20];
    float* out = (float*)d_out;

    __half *xh, *xih, *qk1, *qk2, *ao1, *ao2, *xcat, *hbuf, *ffn, *wt;
    float *xi, *xmid;
    cudaGetSymbolAddress((void**)&xh,   g_xh);
    cudaGetSymbolAddress((void**)&xi,   g_xi);
    cudaGetSymbolAddress((void**)&xih,  g_xih);
    cudaGetSymbolAddress((void**)&qk1,  g_qkv1);
    cudaGetSymbolAddress((void**)&qk2,  g_qkv2);
    cudaGetSymbolAddress((void**)&ao1,  g_ao1);
    cudaGetSymbolAddress((void**)&ao2,  g_ao2);
    cudaGetSymbolAddress((void**)&xcat, g_xcat);
    cudaGetSymbolAddress((void**)&xmid, g_xmid);
    cudaGetSymbolAddress((void**)&hbuf, g_h);
    cudaGetSymbolAddress((void**)&ffn,  g_ffn);
    cudaGetSymbolAddress((void**)&wt,   g_wt);

    cudaFuncSetAttribute(mma_gemm, cudaFuncAttributeMaxDynamicSharedMemorySize, GEMM_SMEM);

    const int MT = B_ * T_;    // 32768
    const int MP = B_ * TP_;   // 32800
    const int MT_TILES = MT / GBM;              // 256
    const int MP_TILES = (MP + GBM - 1) / GBM;  // 257

    // 0. fused prep: all transposes + f2h (one launch)
    PrepArgs pa;
    const float* srcs[8]  = { down_w, up_w, qkv1_w, qkv2_w, proj1_w, proj2_w, ffn_w1, ffn_w2 };
    const uint32_t offs[8] = { O_DOWN, O_UP, O_QKV1, O_QKV2, O_PROJ1, O_PROJ2, O_FFN1, O_FFN2 };
    const int Ks[8] = { DIM_, DIN_, DBR_, DBR_, DBR_, DBR_, DIM_, 2*DIM_ };
    const int Ns[8] = { DIN_, DIM_, 768,  768,  DBR_, DBR_, 2*DIM_, DIM_ };
    int totalTiles = 0;
    for (int i = 0; i < 8; i++) {
        pa.src[i] = srcs[i]; pa.dstOff[i] = offs[i];
        pa.K[i] = Ks[i]; pa.N[i] = Ns[i];
        pa.tiles[i] = (Ns[i] / 32) * (Ks[i] / 32);
        totalTiles += pa.tiles[i];
    }
    pa.x = x; pa.n8 = MT * DIM_ / 8;
    prep_kernel<<<F2H_BLOCKS + totalTiles, 256>>>(pa);

    // 1. down + rmsnorm1 (fp16 out)
    mma_gemm<<<dim3(DIN_/GBN, MT_TILES), 256, GEMM_SMEM>>>(
        xh, wt + O_DOWN, down_b, nullptr, xi, MT, DIN_, DIM_, 0, 0, 0, 0, 0, 0);
    rmsnorm_kernel<<<MT, 128>>>(xi, n1w, xih, DIN_);

    // 2. QKV with fused pack (A gathered from xih with roll)
    mma_gemm<<<dim3(768/GBN, MP_TILES), 256, GEMM_SMEM>>>(
        xih, wt + O_QKV1, qkv1_b, nullptr, qk1, MP, 768, DBR_, 3, 1, 5, 0, 0, 0);
    mma_gemm<<<dim3(768/GBN, MP_TILES), 256, GEMM_SMEM>>>(
        xih, wt + O_QKV2, qkv2_b, nullptr, qk2, MP, 768, DBR_, 3, 1, 10, DBR_, 0, 0);

    // 3. attention (templated)
    attn_kernel<10, NW1_, 5><<<B_ * NW1_ * HBR_ / 4, 128>>>(qk1, ao1, rpb1);
    attn_kernel<20, NW2_, 10><<<B_ * NW2_ * HBR_ / 4, 128>>>(qk2, ao2, rpb2);

    // 4. proj with fused unshift epilogue (writes into xcat)
    mma_gemm<<<dim3(DBR_/GBN, MP_TILES), 256, GEMM_SMEM>>>(
        ao1, wt + O_PROJ1, proj1_b, nullptr, xcat, MP, DBR_, DBR_, 4, 0, 0, 0, 5, 0);
    mma_gemm<<<dim3(DBR_/GBN, MP_TILES), 256, GEMM_SMEM>>>(
        ao2, wt + O_PROJ2, proj2_b, nullptr, xcat, MP, DBR_, DBR_, 4, 0, 0, 0, 10, DBR_);

    // 5. up + residual (fp32 out)
    mma_gemm<<<dim3(DIM_/GBN, MT_TILES), 256, GEMM_SMEM>>>(
        xcat, wt + O_UP, up_b, x, xmid, MT, DIM_, DIN_, 2, 0, 0, 0, 0, 0);

    // 6. rmsnorm2 (fp16 out)
    rmsnorm_kernel<<<MT, 256>>>(xmid, n2w, hbuf, DIM_);

    // 7. FFN1 + GELU (fp16 out)
    mma_gemm<<<dim3(2*DIM_/GBN, MT_TILES), 256, GEMM_SMEM>>>(
        hbuf, wt + O_FFN1, ffn_b1, nullptr, ffn, MT, 2*DIM_, DIM_, 1, 0, 0, 0, 0, 0);

    // 8. FFN2 + residual -> out (fp32)
    mma_gemm<<<dim3(DIM_/GBN, MT_TILES), 256, GEMM_SMEM>>>(
        ffn, wt + O_FFN2, ffn_b2, xmid, out, MT, DIM_, 2*DIM_, 2, 0, 0, 0, 0, 0);
}